// round 10
// baseline (speedup 1.0000x reference)
#include <cuda_runtime.h>
#include <cuda_bf16.h>
#include <cstdint>

#define SS 2048
#define DD 128
#define NTH 512
#define NKT 32                      // 2048 / KTILE, KTILE = 64
#define CTX_ELEMS ((size_t)2 * 16 * 2048 * 128)

// ---- smem byte offsets ----
#define OFF_QH   0                  // 128 x 128 bf16, pitch 256 B, swizzled
#define OFF_QL   32768
#define OFF_KH   65536              // 64 x 128 bf16
#define OFF_KL   81920
#define OFF_VH   98304              // 64 x 128 bf16
#define OFF_VL   114688
#define OFF_PH   131072             // 128 x 64 bf16, pitch 128 B
#define OFF_PL   147456
#define OFF_STA  163840             // A stage slot, 32 KB raw K tile
#define OFF_STB  196608             // B stage slot, 32 KB raw V tile
#define OFF_RS   229376             // float[128]
#define SMEM_SZ  229888

// ---------------- PTX helpers ----------------
__device__ __forceinline__ uint32_t smem_u32(const void* p) {
    return (uint32_t)__cvta_generic_to_shared(p);
}
// swizzled offset, 256 B pitch (128 bf16 cols)
__device__ __forceinline__ uint32_t swoff(int r, int c) {
    return (uint32_t)(r * 256 + ((((c >> 3) ^ (r & 7)) << 4) | ((c & 7) << 1)));
}
// swizzled offset, 128 B pitch (64 bf16 cols)
__device__ __forceinline__ uint32_t swoff64(int r, int c) {
    return (uint32_t)(r * 128 + ((((c >> 3) ^ (r & 7)) << 4) | ((c & 7) << 1)));
}
__device__ __forceinline__ void ldsm4(uint32_t (&r)[4], const void* p) {
    uint32_t a = smem_u32(p);
    asm volatile("ldmatrix.sync.aligned.m8n8.x4.shared.b16 {%0,%1,%2,%3}, [%4];"
                 : "=r"(r[0]), "=r"(r[1]), "=r"(r[2]), "=r"(r[3]) : "r"(a));
}
__device__ __forceinline__ void ldsm4t(uint32_t (&r)[4], const void* p) {
    uint32_t a = smem_u32(p);
    asm volatile("ldmatrix.sync.aligned.m8n8.x4.trans.shared.b16 {%0,%1,%2,%3}, [%4];"
                 : "=r"(r[0]), "=r"(r[1]), "=r"(r[2]), "=r"(r[3]) : "r"(a));
}
__device__ __forceinline__ void mma16816(float (&c)[4], const uint32_t (&a)[4],
                                         uint32_t b0, uint32_t b1) {
    asm volatile(
        "mma.sync.aligned.m16n8k16.row.col.f32.bf16.bf16.f32 "
        "{%0,%1,%2,%3},{%4,%5,%6,%7},{%8,%9},{%0,%1,%2,%3};"
        : "+f"(c[0]), "+f"(c[1]), "+f"(c[2]), "+f"(c[3])
        : "r"(a[0]), "r"(a[1]), "r"(a[2]), "r"(a[3]), "r"(b0), "r"(b1));
}
__device__ __forceinline__ uint32_t pack2(__nv_bfloat16 a, __nv_bfloat16 b) {
    __nv_bfloat162 t = __halves2bfloat162(a, b);
    return *reinterpret_cast<uint32_t*>(&t);
}
__device__ __forceinline__ void cpasync16(uint32_t saddr, const void* g) {
    asm volatile("cp.async.cg.shared.global [%0], [%1], 16;"
                 :: "r"(saddr), "l"(g) : "memory");
}
__device__ __forceinline__ void split8(float4 v0, float4 v1, uint4& hi, uint4& lo) {
    float x[8] = {v0.x, v0.y, v0.z, v0.w, v1.x, v1.y, v1.z, v1.w};
    __nv_bfloat16 h[8], l[8];
#pragma unroll
    for (int j = 0; j < 8; j++) {
        h[j] = __float2bfloat16(x[j]);
        l[j] = __float2bfloat16(x[j] - __bfloat162float(h[j]));
    }
    hi = make_uint4(pack2(h[0], h[1]), pack2(h[2], h[3]),
                    pack2(h[4], h[5]), pack2(h[6], h[7]));
    lo = make_uint4(pack2(l[0], l[1]), pack2(l[2], l[3]),
                    pack2(l[4], l[5]), pack2(l[6], l[7]));
}
#define BARSYNC(id, cnt) \
    asm volatile("bar.sync %0, %1;" :: "r"(id), "r"(cnt) : "memory")
#define BARARRIVE(id, cnt) \
    asm volatile("bar.arrive %0, %1;" :: "r"(id), "r"(cnt) : "memory")

// stage a full 32 KB raw tile (64 rows x 128 f32, contiguous): 128 B/thread
__device__ __forceinline__ void stage_tile(uint32_t sbase, uint32_t stoff,
                                           const float* gsrc, int t) {
    uint32_t sa = sbase + stoff + t * 128;
    const char* g = reinterpret_cast<const char*>(gsrc) + t * 128;
#pragma unroll
    for (int j = 0; j < 8; j++) cpasync16(sa + j * 16, g + j * 16);
    asm volatile("cp.async.commit_group;" ::: "memory");
}

// convert own staged 128 B (row r = t>>2, cols (t&3)*32 .. +31) to split hi/lo
__device__ __forceinline__ void conv_tile(unsigned char* smem, uint32_t stoff,
                                          uint32_t dH, uint32_t dL, int t) {
    asm volatile("cp.async.wait_group 0;" ::: "memory");
    const float4* stg = reinterpret_cast<const float4*>(smem + stoff + t * 128);
    const int r = t >> 2;
    const int c0 = (t & 3) * 32;
#pragma unroll
    for (int j = 0; j < 4; j++) {
        uint4 hi, lo;
        split8(stg[2 * j], stg[2 * j + 1], hi, lo);
        const uint32_t o = swoff(r, c0 + j * 8);
        *reinterpret_cast<uint4*>(smem + dH + o) = hi;
        *reinterpret_cast<uint4*>(smem + dL + o) = lo;
    }
}

// ---------------- main kernel ----------------
__global__ void __launch_bounds__(NTH, 1)
sdpa_kernel(const float* __restrict__ Q, const float* __restrict__ K,
            const float* __restrict__ V, const int* __restrict__ mask,
            const float* __restrict__ scalep, float* __restrict__ out) {
    extern __shared__ unsigned char smem[];
    const uint32_t sbase = smem_u32(smem);
    float* rsm = reinterpret_cast<float*>(smem + OFF_RS);

    const int tid  = threadIdx.x;
    const int lane = tid & 31;
    const int warp = tid >> 5;
    const bool grpA = (warp < 8);
    const int t = grpA ? tid : tid - 256;     // group-local thread id

    const int bh = blockIdx.x >> 4;
    const int qt = blockIdx.x & 15;
    const int b  = bh >> 4;
    const int qbase = qt * 128;

    const float scale = *scalep;
    const float* Qg = Q + ((size_t)bh * SS + qbase) * DD;
    const float* Kg = K + (size_t)bh * SS * DD;
    const float* Vg = V + (size_t)bh * SS * DD;
    const int*   mb = mask + (size_t)b * SS * SS;
    float* ctx = out + ((size_t)bh * SS + qbase) * DD;
    float* att = out + CTX_ELEMS + ((size_t)bh * SS + qbase) * SS;

    // prologue: stage first tiles; load Q split (all threads, 32 elems each)
    if (grpA) stage_tile(sbase, OFF_STA, Kg, t);
    else      stage_tile(sbase, OFF_STB, Vg, t);
    {
        const int r = tid >> 2;
        const int c0 = (tid & 3) * 32;
        const float4* qr = reinterpret_cast<const float4*>(Qg + (size_t)r * DD + c0);
#pragma unroll
        for (int j = 0; j < 4; j++) {
            uint4 hi, lo;
            split8(qr[2 * j], qr[2 * j + 1], hi, lo);
            const uint32_t o = swoff(r, c0 + j * 8);
            *reinterpret_cast<uint4*>(smem + OFF_QH + o) = hi;
            *reinterpret_cast<uint4*>(smem + OFF_QL + o) = lo;
        }
    }
    if (tid < 128) rsm[tid] = 0.f;
    __syncthreads();

    if (grpA) {
        // ============ GROUP A: convert K, S = Q K^T, exp -> P ============
        const int wm = warp >> 1;     // 0..3
        const int wn = warp & 1;      // 0..1
#pragma unroll 1
        for (int kt = 0; kt < NKT; kt++) {
            conv_tile(smem, OFF_STA, OFF_KH, OFF_KL, t);
            const float* nK = (kt + 1 < NKT) ? Kg + (size_t)(kt + 1) * 64 * DD : Kg;
            stage_tile(sbase, OFF_STA, nK, t);
            BARSYNC(3, 256);                       // K tile visible in A

            float sacc[2][4][4];
#pragma unroll
            for (int im = 0; im < 2; im++)
#pragma unroll
                for (int j = 0; j < 4; j++)
#pragma unroll
                    for (int c = 0; c < 4; c++) sacc[im][j][c] = 0.f;

#pragma unroll 1
            for (int kk = 0; kk < 8; kk++) {
                uint32_t aH[2][4], aL[2][4];
#pragma unroll
                for (int im = 0; im < 2; im++) {
                    const uint32_t ao = swoff(wm * 32 + im * 16 + (lane & 15),
                                              kk * 16 + (lane >> 4) * 8);
                    ldsm4(aH[im], smem + OFF_QH + ao);
                    ldsm4(aL[im], smem + OFF_QL + ao);
                }
#pragma unroll
                for (int j2 = 0; j2 < 2; j2++) {
                    const uint32_t bo =
                        swoff(wn * 32 + j2 * 16 + (lane >> 4) * 8 + (lane & 7),
                              kk * 16 + ((lane >> 3) & 1) * 8);
                    uint32_t bH[4], bL[4];
                    ldsm4(bH, smem + OFF_KH + bo);
                    ldsm4(bL, smem + OFF_KL + bo);
#pragma unroll
                    for (int im = 0; im < 2; im++) {
                        mma16816(sacc[im][2 * j2 + 0], aH[im], bH[0], bH[1]);
                        mma16816(sacc[im][2 * j2 + 1], aH[im], bH[2], bH[3]);
                        mma16816(sacc[im][2 * j2 + 0], aH[im], bL[0], bL[1]);
                        mma16816(sacc[im][2 * j2 + 1], aH[im], bL[2], bL[3]);
                        mma16816(sacc[im][2 * j2 + 0], aL[im], bH[0], bH[1]);
                        mma16816(sacc[im][2 * j2 + 1], aL[im], bH[2], bH[3]);
                    }
                }
            }
            BARSYNC(3, 256);                       // all A done reading K
            if (kt > 0) BARSYNC(2, NTH);           // wait P buffer free

            // epilogue: exp -> P hi/lo (no mask here)
#pragma unroll
            for (int im = 0; im < 2; im++)
#pragma unroll
                for (int half = 0; half < 2; half++) {
                    const int ql = wm * 32 + im * 16 + (lane >> 2) + half * 8;
#pragma unroll
                    for (int jn = 0; jn < 4; jn++) {
                        const int nc = wn * 32 + jn * 8 + (lane & 3) * 2;
                        float e0 = __expf(sacc[im][jn][half * 2 + 0] * scale);
                        float e1 = __expf(sacc[im][jn][half * 2 + 1] * scale);
                        __nv_bfloat16 h0 = __float2bfloat16(e0);
                        __nv_bfloat16 h1 = __float2bfloat16(e1);
                        __nv_bfloat16 l0 = __float2bfloat16(e0 - __bfloat162float(h0));
                        __nv_bfloat16 l1 = __float2bfloat16(e1 - __bfloat162float(h1));
                        const uint32_t po = swoff64(ql, nc);
                        *reinterpret_cast<uint32_t*>(smem + OFF_PH + po) = pack2(h0, h1);
                        *reinterpret_cast<uint32_t*>(smem + OFF_PL + po) = pack2(l0, l1);
                    }
                }
            __threadfence_block();                 // P stores visible before arrive
            BARARRIVE(1, NTH);                     // P(kt) ready
        }
        asm volatile("cp.async.wait_group 0;" ::: "memory");
    } else {
        // ============ GROUP B: convert V, att phase, O += P V ============
        const int w  = warp - 8;
        const int wm = w >> 1;        // 0..3
        const int wn = w & 1;         // 0..1
        float oacc[2][8][4];
#pragma unroll
        for (int im = 0; im < 2; im++)
#pragma unroll
            for (int j = 0; j < 8; j++)
#pragma unroll
                for (int c = 0; c < 4; c++) oacc[im][j][c] = 0.f;

#pragma unroll 1
        for (int kt = 0; kt < NKT; kt++) {
            conv_tile(smem, OFF_STB, OFF_VH, OFF_VL, t);
            const float* nV = (kt + 1 < NKT) ? Vg + (size_t)(kt + 1) * 64 * DD : Vg;
            stage_tile(sbase, OFF_STB, nV, t);
            BARSYNC(4, 256);                       // V tile visible in B
            BARSYNC(1, NTH);                       // wait P(kt) ready

            // att phase: warp w owns rows w*16..+15; lane covers 2 cols
#pragma unroll 1
            for (int i = 0; i < 16; i++) {
                const int r = w * 16 + i;
                const uint32_t po = swoff64(r, lane * 2);
                uint32_t hp = *reinterpret_cast<uint32_t*>(smem + OFF_PH + po);
                uint32_t lp = *reinterpret_cast<uint32_t*>(smem + OFF_PL + po);
                __nv_bfloat162 h2 = *reinterpret_cast<__nv_bfloat162*>(&hp);
                __nv_bfloat162 l2 = *reinterpret_cast<__nv_bfloat162*>(&lp);
                float e0 = __bfloat162float(__low2bfloat16(h2)) +
                           __bfloat162float(__low2bfloat16(l2));
                float e1 = __bfloat162float(__high2bfloat16(h2)) +
                           __bfloat162float(__high2bfloat16(l2));
                int2 mv = *reinterpret_cast<const int2*>(
                    mb + (size_t)(qbase + r) * SS + kt * 64 + lane * 2);
                if (!mv.x) { e0 = 0.f; hp &= 0xffff0000u; lp &= 0xffff0000u; }
                if (!mv.y) { e1 = 0.f; hp &= 0x0000ffffu; lp &= 0x0000ffffu; }
                *reinterpret_cast<float2*>(att + (size_t)r * SS + kt * 64 + lane * 2) =
                    make_float2(e0, e1);
                *reinterpret_cast<uint32_t*>(smem + OFF_PH + po) = hp;
                *reinterpret_cast<uint32_t*>(smem + OFF_PL + po) = lp;
                float s = e0 + e1;
                s += __shfl_xor_sync(0xffffffff, s, 16);
                s += __shfl_xor_sync(0xffffffff, s, 8);
                s += __shfl_xor_sync(0xffffffff, s, 4);
                s += __shfl_xor_sync(0xffffffff, s, 2);
                s += __shfl_xor_sync(0xffffffff, s, 1);
                if (lane == 0) rsm[r] += s;
            }
            BARSYNC(4, 256);                       // masked P visible in B

            // PV gemm: warp tile 32x64, k-dim 64 (kk 0..3)
#pragma unroll 1
            for (int kk = 0; kk < 4; kk++) {
                uint32_t aH[2][4], aL[2][4];
#pragma unroll
                for (int im = 0; im < 2; im++) {
                    const uint32_t ao = swoff64(wm * 32 + im * 16 + (lane & 15),
                                                kk * 16 + (lane >> 4) * 8);
                    ldsm4(aH[im], smem + OFF_PH + ao);
                    ldsm4(aL[im], smem + OFF_PL + ao);
                }
#pragma unroll
                for (int j2 = 0; j2 < 4; j2++) {
                    const uint32_t bo =
                        swoff(kk * 16 + (lane & 7) + ((lane >> 3) & 1) * 8,
                              wn * 64 + j2 * 16 + (lane >> 4) * 8);
                    uint32_t bH[4], bL[4];
                    ldsm4t(bH, smem + OFF_VH + bo);
                    ldsm4t(bL, smem + OFF_VL + bo);
#pragma unroll
                    for (int im = 0; im < 2; im++) {
                        mma16816(oacc[im][2 * j2 + 0], aH[im], bH[0], bH[1]);
                        mma16816(oacc[im][2 * j2 + 1], aH[im], bH[2], bH[3]);
                        mma16816(oacc[im][2 * j2 + 0], aH[im], bL[0], bL[1]);
                        mma16816(oacc[im][2 * j2 + 1], aH[im], bL[2], bL[3]);
                        mma16816(oacc[im][2 * j2 + 0], aL[im], bH[0], bH[1]);
                        mma16816(oacc[im][2 * j2 + 1], aL[im], bH[2], bH[3]);
                    }
                }
            }
            BARSYNC(4, 256);                       // all B done with P + V
            BARARRIVE(2, NTH);                     // P buffer free
        }
        asm volatile("cp.async.wait_group 0;" ::: "memory");

        __syncthreads();                           // joint 1 (A matches below)
        if (t < 128) rsm[t] = 1.f / rsm[t];        // FIX: group-local id 0..127
        __syncthreads();                           // joint 2
#pragma unroll
        for (int im = 0; im < 2; im++)
#pragma unroll
            for (int half = 0; half < 2; half++) {
                const int ql = wm * 32 + im * 16 + (lane >> 2) + half * 8;
                const float rn = rsm[ql];
                float* crow = ctx + (size_t)ql * DD;
#pragma unroll
                for (int jn = 0; jn < 8; jn++) {
                    const int d0 = wn * 64 + jn * 8 + (lane & 3) * 2;
                    *reinterpret_cast<float2*>(crow + d0) =
                        make_float2(oacc[im][jn][half * 2 + 0] * rn,
                                    oacc[im][jn][half * 2 + 1] * rn);
                }
            }
    }
    if (grpA) {          // A joins the two syncthreads B executed
        __syncthreads();
        __syncthreads();
    }
    __syncthreads();     // rowsum inverses + ctx done everywhere

    // ---- normalize this CTA's attention slice in place (all 16 warps) ----
    float2* ap = reinterpret_cast<float2*>(att);
#pragma unroll 4
    for (int i = tid; i < 128 * SS / 2; i += NTH) {
        float rn = rsm[i >> 10];   // 1024 float2 per row
        float2 v = ap[i];
        v.x *= rn;
        v.y *= rn;
        ap[i] = v;
    }
}

// ---------------- launch ----------------
extern "C" void kernel_launch(void* const* d_in, const int* in_sizes, int n_in,
                              void* d_out, int out_size) {
    const float* Q = (const float*)d_in[0];
    const float* K = (const float*)d_in[1];
    const float* V = (const float*)d_in[2];
    const int*   M = (const int*)d_in[3];
    const float* scale = (const float*)d_in[4];
    float* out = (float*)d_out;

    cudaFuncSetAttribute(sdpa_kernel, cudaFuncAttributeMaxDynamicSharedMemorySize,
                         SMEM_SZ);
    sdpa_kernel<<<512, NTH, SMEM_SZ>>>(Q, K, V, M, scale, out);
}

// round 11
// speedup vs baseline: 1.5316x; 1.5316x over previous
#include <cuda_runtime.h>
#include <cuda_bf16.h>
#include <cstdint>

#define SS 2048
#define DD 128
#define NTH 256
#define NKT 32                      // 2048 / KTILE, KTILE = 64
#define CTX_ELEMS ((size_t)2 * 16 * 2048 * 128)

// ---- smem byte offsets (per-CTA total 98560 B -> 2 CTAs/SM) ----
#define OFF_QH   0                  // 64 x 128 bf16, pitch 256 B, swizzled
#define OFF_QL   16384
#define OFF_KVH  32768              // 64 x 128 bf16 (K, then V)
#define OFF_KVL  49152
#define OFF_PH   65536              // 64 x 64 bf16, pitch 128 B
#define OFF_PL   73728
#define OFF_STG  81920              // 2 slots x 8192 raw chunk (16 rows x 128 f32)
#define OFF_RS   98304              // float[64]
#define SMEM_SZ  98560

// ---------------- PTX helpers ----------------
__device__ __forceinline__ uint32_t smem_u32(const void* p) {
    return (uint32_t)__cvta_generic_to_shared(p);
}
// swizzled offset, 256 B pitch (128 bf16 cols)
__device__ __forceinline__ uint32_t swoff(int r, int c) {
    return (uint32_t)(r * 256 + ((((c >> 3) ^ (r & 7)) << 4) | ((c & 7) << 1)));
}
// swizzled offset, 128 B pitch (64 bf16 cols)
__device__ __forceinline__ uint32_t swoff64(int r, int c) {
    return (uint32_t)(r * 128 + ((((c >> 3) ^ (r & 7)) << 4) | ((c & 7) << 1)));
}
__device__ __forceinline__ void ldsm4(uint32_t (&r)[4], const void* p) {
    uint32_t a = smem_u32(p);
    asm volatile("ldmatrix.sync.aligned.m8n8.x4.shared.b16 {%0,%1,%2,%3}, [%4];"
                 : "=r"(r[0]), "=r"(r[1]), "=r"(r[2]), "=r"(r[3]) : "r"(a));
}
__device__ __forceinline__ void ldsm4t(uint32_t (&r)[4], const void* p) {
    uint32_t a = smem_u32(p);
    asm volatile("ldmatrix.sync.aligned.m8n8.x4.trans.shared.b16 {%0,%1,%2,%3}, [%4];"
                 : "=r"(r[0]), "=r"(r[1]), "=r"(r[2]), "=r"(r[3]) : "r"(a));
}
__device__ __forceinline__ void mma16816(float (&c)[4], const uint32_t (&a)[4],
                                         uint32_t b0, uint32_t b1) {
    asm volatile(
        "mma.sync.aligned.m16n8k16.row.col.f32.bf16.bf16.f32 "
        "{%0,%1,%2,%3},{%4,%5,%6,%7},{%8,%9},{%0,%1,%2,%3};"
        : "+f"(c[0]), "+f"(c[1]), "+f"(c[2]), "+f"(c[3])
        : "r"(a[0]), "r"(a[1]), "r"(a[2]), "r"(a[3]), "r"(b0), "r"(b1));
}
__device__ __forceinline__ uint32_t pack2(__nv_bfloat16 a, __nv_bfloat16 b) {
    __nv_bfloat162 t = __halves2bfloat162(a, b);
    return *reinterpret_cast<uint32_t*>(&t);
}
__device__ __forceinline__ void cpasync16(uint32_t saddr, const void* g) {
    asm volatile("cp.async.cg.shared.global [%0], [%1], 16;"
                 :: "r"(saddr), "l"(g) : "memory");
}
__device__ __forceinline__ void split8(float4 v0, float4 v1, uint4& hi, uint4& lo) {
    float x[8] = {v0.x, v0.y, v0.z, v0.w, v1.x, v1.y, v1.z, v1.w};
    __nv_bfloat16 h[8], l[8];
#pragma unroll
    for (int j = 0; j < 8; j++) {
        h[j] = __float2bfloat16(x[j]);
        l[j] = __float2bfloat16(x[j] - __bfloat162float(h[j]));
    }
    hi = make_uint4(pack2(h[0], h[1]), pack2(h[2], h[3]),
                    pack2(h[4], h[5]), pack2(h[6], h[7]));
    lo = make_uint4(pack2(l[0], l[1]), pack2(l[2], l[3]),
                    pack2(l[4], l[5]), pack2(l[6], l[7]));
}

// stage one 8 KB chunk (16 rows x 128 f32); thread stages its own 32 B
__device__ __forceinline__ void stage_chunk(uint32_t sbase, int slot,
                                            const float* gsrc, int tid) {
    uint32_t sa = sbase + OFF_STG + slot * 8192 + tid * 32;
    const char* g = reinterpret_cast<const char*>(gsrc) + tid * 32;
    cpasync16(sa, g);
    cpasync16(sa + 16, g + 16);
    asm volatile("cp.async.commit_group;" ::: "memory");
}

// barrier-free convert: wait own staged chunk (self-owned bytes), split rows
// [ch*16, ch*16+16) into KV buffers, then restage slot with next_gsrc.
__device__ __forceinline__ void conv_chunk(unsigned char* smem, uint32_t sbase,
                                           int slot, int ch,
                                           const float* next_gsrc, int tid) {
    asm volatile("cp.async.wait_group 1;" ::: "memory");
    const float* stg = reinterpret_cast<const float*>(smem + OFF_STG + slot * 8192);
    const int r  = ch * 16 + (tid >> 4);
    const int c0 = (tid & 15) * 8;
    float4 v0 = *reinterpret_cast<const float4*>(stg + tid * 8);
    float4 v1 = *reinterpret_cast<const float4*>(stg + tid * 8 + 4);
    uint4 hi, lo;
    split8(v0, v1, hi, lo);
    const uint32_t off = swoff(r, c0);
    *reinterpret_cast<uint4*>(smem + OFF_KVH + off) = hi;
    *reinterpret_cast<uint4*>(smem + OFF_KVL + off) = lo;
    stage_chunk(sbase, slot, next_gsrc, tid);
}

// ---------------- main kernel ----------------
__global__ void __launch_bounds__(NTH, 2)
sdpa_kernel(const float* __restrict__ Q, const float* __restrict__ K,
            const float* __restrict__ V, const int* __restrict__ mask,
            const float* __restrict__ scalep, float* __restrict__ out) {
    extern __shared__ unsigned char smem[];
    const uint32_t sbase = smem_u32(smem);
    float* rsm = reinterpret_cast<float*>(smem + OFF_RS);

    const int tid  = threadIdx.x;
    const int lane = tid & 31;
    const int warp = tid >> 5;
    const int wm = warp >> 1;   // 0..3 -> m offset 16*wm
    const int wn = warp & 1;    // 0..1

    const int bh = blockIdx.x >> 5;       // 0..31
    const int qt = blockIdx.x & 31;       // 0..31 (64-row q tiles)
    const int b  = bh >> 4;               // H = 16
    const int qbase = qt * 64;

    const float scale = *scalep;
    const float* Qg = Q + ((size_t)bh * SS + qbase) * DD;
    const float* Kg = K + (size_t)bh * SS * DD;
    const float* Vg = V + (size_t)bh * SS * DD;
    const int*   mb = mask + (size_t)b * SS * SS;
    float* ctx = out + ((size_t)bh * SS + qbase) * DD;
    float* att = out + CTX_ELEMS + ((size_t)bh * SS + qbase) * SS;

    // prologue: stage K(0) chunks 0,1; load Q split (thread owns 32 floats)
    stage_chunk(sbase, 0, Kg + 0 * 2048, tid);
    stage_chunk(sbase, 1, Kg + 1 * 2048, tid);
    {
        const int r = tid >> 2;           // 0..63
        const int c0 = (tid & 3) * 32;
        const float4* qr = reinterpret_cast<const float4*>(Qg + (size_t)r * DD + c0);
#pragma unroll
        for (int j = 0; j < 4; j++) {
            uint4 hi, lo;
            split8(qr[2 * j], qr[2 * j + 1], hi, lo);
            const uint32_t o = swoff(r, c0 + j * 8);
            *reinterpret_cast<uint4*>(smem + OFF_QH + o) = hi;
            *reinterpret_cast<uint4*>(smem + OFF_QL + o) = lo;
        }
    }
    if (tid < 64) rsm[tid] = 0.f;

    float oacc[8][4];
#pragma unroll
    for (int j = 0; j < 8; j++)
#pragma unroll
        for (int c = 0; c < 4; c++) oacc[j][c] = 0.f;

#pragma unroll 1
    for (int kt = 0; kt < NKT; kt++) {
        const float* Kt = Kg + (size_t)kt * 64 * DD;
        const float* Vt = Vg + (size_t)kt * 64 * DD;
        const float* Nt = (kt + 1 < NKT) ? Kg + (size_t)(kt + 1) * 64 * DD : Kg;

        __syncthreads();   // bar A: prev PV done reading KV before K overwrite

        conv_chunk(smem, sbase, 0, 0, Kt + 2 * 2048, tid);
        conv_chunk(smem, sbase, 1, 1, Kt + 3 * 2048, tid);
        conv_chunk(smem, sbase, 0, 2, Vt + 0 * 2048, tid);
        conv_chunk(smem, sbase, 1, 3, Vt + 1 * 2048, tid);

        __syncthreads();   // bar B: K tile visible

        // ---- S = Q K^T  (warp tile 16x32, K=128) ----
        float sacc[4][4];
#pragma unroll
        for (int j = 0; j < 4; j++)
#pragma unroll
            for (int c = 0; c < 4; c++) sacc[j][c] = 0.f;

#pragma unroll 1
        for (int kk = 0; kk < 8; kk++) {
            uint32_t aH[4], aL[4];
            const uint32_t ao = swoff(wm * 16 + (lane & 15),
                                      kk * 16 + (lane >> 4) * 8);
            ldsm4(aH, smem + OFF_QH + ao);
            ldsm4(aL, smem + OFF_QL + ao);
#pragma unroll
            for (int j2 = 0; j2 < 2; j2++) {
                const uint32_t bo =
                    swoff(wn * 32 + j2 * 16 + (lane >> 4) * 8 + (lane & 7),
                          kk * 16 + ((lane >> 3) & 1) * 8);
                uint32_t bH[4], bL[4];
                ldsm4(bH, smem + OFF_KVH + bo);
                ldsm4(bL, smem + OFF_KVL + bo);
                mma16816(sacc[2 * j2 + 0], aH, bH[0], bH[1]);
                mma16816(sacc[2 * j2 + 1], aH, bH[2], bH[3]);
                mma16816(sacc[2 * j2 + 0], aH, bL[0], bL[1]);
                mma16816(sacc[2 * j2 + 1], aH, bL[2], bL[3]);
                mma16816(sacc[2 * j2 + 0], aL, bH[0], bH[1]);
                mma16816(sacc[2 * j2 + 1], aL, bH[2], bH[3]);
            }
        }

        // ---- epilogue: raw exp -> P hi/lo ----
#pragma unroll
        for (int half = 0; half < 2; half++) {
            const int ql = wm * 16 + (lane >> 2) + half * 8;
#pragma unroll
            for (int jn = 0; jn < 4; jn++) {
                const int nc = wn * 32 + jn * 8 + (lane & 3) * 2;
                float e0 = __expf(sacc[jn][half * 2 + 0] * scale);
                float e1 = __expf(sacc[jn][half * 2 + 1] * scale);
                __nv_bfloat16 h0 = __float2bfloat16(e0);
                __nv_bfloat16 h1 = __float2bfloat16(e1);
                __nv_bfloat16 l0 = __float2bfloat16(e0 - __bfloat162float(h0));
                __nv_bfloat16 l1 = __float2bfloat16(e1 - __bfloat162float(h1));
                const uint32_t po = swoff64(ql, nc);
                *reinterpret_cast<uint32_t*>(smem + OFF_PH + po) = pack2(h0, h1);
                *reinterpret_cast<uint32_t*>(smem + OFF_PL + po) = pack2(l0, l1);
            }
        }

        __syncthreads();   // bar C: P raw visible; S-gemm KV reads done

        conv_chunk(smem, sbase, 0, 0, Vt + 2 * 2048, tid);
        conv_chunk(smem, sbase, 1, 1, Vt + 3 * 2048, tid);
        conv_chunk(smem, sbase, 0, 2, Nt + 0 * 2048, tid);
        conv_chunk(smem, sbase, 1, 3, Nt + 1 * 2048, tid);

        // ---- att phase: warp owns rows warp*8..+7, lane -> 2 cols ----
        {
            const int cc = lane * 2;
#pragma unroll 1
            for (int i = 0; i < 8; i++) {
                const int r = warp * 8 + i;
                const uint32_t po = swoff64(r, cc);
                uint32_t hp = *reinterpret_cast<uint32_t*>(smem + OFF_PH + po);
                uint32_t lp = *reinterpret_cast<uint32_t*>(smem + OFF_PL + po);
                __nv_bfloat162 h2 = *reinterpret_cast<__nv_bfloat162*>(&hp);
                __nv_bfloat162 l2 = *reinterpret_cast<__nv_bfloat162*>(&lp);
                float e0 = __bfloat162float(__low2bfloat16(h2)) +
                           __bfloat162float(__low2bfloat16(l2));
                float e1 = __bfloat162float(__high2bfloat16(h2)) +
                           __bfloat162float(__high2bfloat16(l2));
                int2 mv = *reinterpret_cast<const int2*>(
                    mb + (size_t)(qbase + r) * SS + kt * 64 + cc);
                if (!mv.x) { e0 = 0.f; hp &= 0xffff0000u; lp &= 0xffff0000u; }
                if (!mv.y) { e1 = 0.f; hp &= 0x0000ffffu; lp &= 0x0000ffffu; }
                *reinterpret_cast<float2*>(att + (size_t)r * SS + kt * 64 + cc) =
                    make_float2(e0, e1);
                *reinterpret_cast<uint32_t*>(smem + OFF_PH + po) = hp;
                *reinterpret_cast<uint32_t*>(smem + OFF_PL + po) = lp;
                float s = e0 + e1;
                s += __shfl_xor_sync(0xffffffff, s, 16);
                s += __shfl_xor_sync(0xffffffff, s, 8);
                s += __shfl_xor_sync(0xffffffff, s, 4);
                s += __shfl_xor_sync(0xffffffff, s, 2);
                s += __shfl_xor_sync(0xffffffff, s, 1);
                if (lane == 0) rsm[r] += s;
            }
        }

        __syncthreads();   // bar D: V + masked P visible

        // ---- O += P V  (warp tile 16x64, K=64; V row-major -> trans B) ----
#pragma unroll 1
        for (int kk = 0; kk < 4; kk++) {
            uint32_t aH[4], aL[4];
            const uint32_t ao = swoff64(wm * 16 + (lane & 15),
                                        kk * 16 + (lane >> 4) * 8);
            ldsm4(aH, smem + OFF_PH + ao);
            ldsm4(aL, smem + OFF_PL + ao);
#pragma unroll
            for (int j2 = 0; j2 < 4; j2++) {
                const uint32_t bo =
                    swoff(kk * 16 + (lane & 7) + ((lane >> 3) & 1) * 8,
                          wn * 64 + j2 * 16 + (lane >> 4) * 8);
                uint32_t bH[4], bL[4];
                ldsm4t(bH, smem + OFF_KVH + bo);
                ldsm4t(bL, smem + OFF_KVL + bo);
                mma16816(oacc[2 * j2 + 0], aH, bH[0], bH[1]);
                mma16816(oacc[2 * j2 + 1], aH, bH[2], bH[3]);
                mma16816(oacc[2 * j2 + 0], aH, bL[0], bL[1]);
                mma16816(oacc[2 * j2 + 1], aH, bL[2], bL[3]);
                mma16816(oacc[2 * j2 + 0], aL, bH[0], bH[1]);
                mma16816(oacc[2 * j2 + 1], aL, bH[2], bH[3]);
            }
        }
    }

    asm volatile("cp.async.wait_group 0;" ::: "memory");
    __syncthreads();
    if (tid < 64) rsm[tid] = 1.f / rsm[tid];
    __syncthreads();

    // ---- write context = O * rnorm ----
#pragma unroll
    for (int half = 0; half < 2; half++) {
        const int ql = wm * 16 + (lane >> 2) + half * 8;
        const float rn = rsm[ql];
        float* crow = ctx + (size_t)ql * DD;
#pragma unroll
        for (int jn = 0; jn < 8; jn++) {
            const int d0 = wn * 64 + jn * 8 + (lane & 3) * 2;
            *reinterpret_cast<float2*>(crow + d0) =
                make_float2(oacc[jn][half * 2 + 0] * rn,
                            oacc[jn][half * 2 + 1] * rn);
        }
    }

    // ---- normalize this CTA's attention slice in place ----
    float2* ap = reinterpret_cast<float2*>(att);
#pragma unroll 4
    for (int i = tid; i < 64 * SS / 2; i += NTH) {
        float rn = rsm[i >> 10];   // 1024 float2 per row
        float2 v = ap[i];
        v.x *= rn;
        v.y *= rn;
        ap[i] = v;
    }
}

// ---------------- launch ----------------
extern "C" void kernel_launch(void* const* d_in, const int* in_sizes, int n_in,
                              void* d_out, int out_size) {
    const float* Q = (const float*)d_in[0];
    const float* K = (const float*)d_in[1];
    const float* V = (const float*)d_in[2];
    const int*   M = (const int*)d_in[3];
    const float* scale = (const float*)d_in[4];
    float* out = (float*)d_out;

    cudaFuncSetAttribute(sdpa_kernel, cudaFuncAttributeMaxDynamicSharedMemorySize,
                         SMEM_SZ);
    sdpa_kernel<<<1024, NTH, SMEM_SZ>>>(Q, K, V, M, scale, out);
}

// round 12
// speedup vs baseline: 2.3339x; 1.5239x over previous
#include <cuda_runtime.h>
#include <cuda_fp16.h>
#include <cstdint>

// Problem constants
#define SS 2048
#define DD 128
#define NTH 512
#define CTX_ELEMS ((size_t)2 * 16 * 2048 * 128)   // 8388608

// ---- dynamic smem byte offsets (swizzled buffers, 256 B row pitch) ----
#define OFF_QH  0                  // 128x128 fp16 hi
#define OFF_QL  32768              // 128x128 fp16 lo
#define OFF_KV  65536              // 128x128 fp16 (K then V), single precision
#define OFF_PH  98304              // 128x128 fp16 hi
#define OFF_PL  131072             // 128x128 fp16 lo
#define OFF_STG 163840             // 2 slots x 16384 raw fp32 chunks
#define OFF_RS  196608             // float[128]
#define SMEM_SZ 197120

// ---------------- PTX helpers ----------------
__device__ __forceinline__ uint32_t smem_u32(const void* p) {
    return (uint32_t)__cvta_generic_to_shared(p);
}

// byte offset of fp16 element (r, c) in swizzled 128x128 tile (row = 256 B)
__device__ __forceinline__ uint32_t swoff(int r, int c) {
    return (uint32_t)(r * 256 + ((((c >> 3) ^ (r & 7)) << 4) | ((c & 7) << 1)));
}

__device__ __forceinline__ void ldsm4(uint32_t (&r)[4], const void* p) {
    uint32_t a = smem_u32(p);
    asm volatile("ldmatrix.sync.aligned.m8n8.x4.shared.b16 {%0,%1,%2,%3}, [%4];"
                 : "=r"(r[0]), "=r"(r[1]), "=r"(r[2]), "=r"(r[3]) : "r"(a));
}
__device__ __forceinline__ void ldsm4t(uint32_t (&r)[4], const void* p) {
    uint32_t a = smem_u32(p);
    asm volatile("ldmatrix.sync.aligned.m8n8.x4.trans.shared.b16 {%0,%1,%2,%3}, [%4];"
                 : "=r"(r[0]), "=r"(r[1]), "=r"(r[2]), "=r"(r[3]) : "r"(a));
}
__device__ __forceinline__ void mma16816(float (&c)[4], const uint32_t (&a)[4],
                                         uint32_t b0, uint32_t b1) {
    asm volatile(
        "mma.sync.aligned.m16n8k16.row.col.f32.f16.f16.f32 "
        "{%0,%1,%2,%3},{%4,%5,%6,%7},{%8,%9},{%0,%1,%2,%3};"
        : "+f"(c[0]), "+f"(c[1]), "+f"(c[2]), "+f"(c[3])
        : "r"(a[0]), "r"(a[1]), "r"(a[2]), "r"(a[3]), "r"(b0), "r"(b1));
}
__device__ __forceinline__ uint32_t pack2h(__half a, __half b) {
    __half2 t = __halves2half2(a, b);
    return *reinterpret_cast<uint32_t*>(&t);
}
__device__ __forceinline__ void cpasync16(uint32_t saddr, const void* g) {
    asm volatile("cp.async.cg.shared.global [%0], [%1], 16;"
                 :: "r"(saddr), "l"(g) : "memory");
}

// split 8 fp32 -> fp16 hi + fp16 lo residual
__device__ __forceinline__ void split8h(float4 v0, float4 v1, uint4& hi, uint4& lo) {
    float x[8] = {v0.x, v0.y, v0.z, v0.w, v1.x, v1.y, v1.z, v1.w};
    __half h[8], l[8];
#pragma unroll
    for (int j = 0; j < 8; j++) {
        h[j] = __float2half_rn(x[j]);
        l[j] = __float2half_rn(x[j] - __half2float(h[j]));
    }
    hi = make_uint4(pack2h(h[0], h[1]), pack2h(h[2], h[3]),
                    pack2h(h[4], h[5]), pack2h(h[6], h[7]));
    lo = make_uint4(pack2h(l[0], l[1]), pack2h(l[2], l[3]),
                    pack2h(l[4], l[5]), pack2h(l[6], l[7]));
}
// convert 8 fp32 -> single fp16
__device__ __forceinline__ void cvt8h(float4 v0, float4 v1, uint4& hi) {
    hi = make_uint4(
        pack2h(__float2half_rn(v0.x), __float2half_rn(v0.y)),
        pack2h(__float2half_rn(v0.z), __float2half_rn(v0.w)),
        pack2h(__float2half_rn(v1.x), __float2half_rn(v1.y)),
        pack2h(__float2half_rn(v1.z), __float2half_rn(v1.w)));
}

// stage one 16 KB chunk (32 rows x 128 fp32); thread stages its own 32 B
__device__ __forceinline__ void stage_chunk(uint32_t sbase, int slot,
                                            const float* gsrc, int tid) {
    uint32_t sa = sbase + OFF_STG + slot * 16384 + tid * 32;
    const char* g = reinterpret_cast<const char*>(gsrc) + tid * 32;
    cpasync16(sa, g);
    cpasync16(sa + 16, g + 16);
    asm volatile("cp.async.commit_group;" ::: "memory");
}

// barrier-free: wait own staged chunk, convert rows [ch*32, +32) into KV
// (single fp16), then restage slot with next_gsrc.
__device__ __forceinline__ void conv_chunk(unsigned char* smem, uint32_t sbase,
                                           int slot, int ch,
                                           const float* next_gsrc, int tid) {
    asm volatile("cp.async.wait_group 1;" ::: "memory");
    const float* stg = reinterpret_cast<const float*>(smem + OFF_STG + slot * 16384);
    const int rl = tid >> 4;
    const int c  = (tid & 15) * 8;
    const int r  = ch * 32 + rl;
    float4 v0 = *reinterpret_cast<const float4*>(stg + rl * 128 + c);
    float4 v1 = *reinterpret_cast<const float4*>(stg + rl * 128 + c + 4);
    uint4 hi;
    cvt8h(v0, v1, hi);
    const uint32_t off = (uint32_t)(r * 256 + ((((c >> 3) ^ (r & 7))) << 4));
    *reinterpret_cast<uint4*>(smem + OFF_KV + off) = hi;
    stage_chunk(sbase, slot, next_gsrc, tid);
}

// 32x32 warp-tile GEMM over K=128: A split hi/lo, B single (2 products)
template <bool TRANSB>
__device__ __forceinline__ void gemm_tile(const unsigned char* smem,
                                          uint32_t offAH, uint32_t offAL,
                                          uint32_t offB,
                                          float (&acc)[2][4][4],
                                          int wm, int wn, int lane) {
#pragma unroll 1
    for (int kk = 0; kk < 8; kk++) {
        uint32_t aH[2][4], aL[2][4];
#pragma unroll
        for (int im = 0; im < 2; im++) {
            const uint32_t ao = swoff(wm * 32 + im * 16 + (lane & 15),
                                      kk * 16 + (lane >> 4) * 8);
            ldsm4(aH[im], smem + offAH + ao);
            ldsm4(aL[im], smem + offAL + ao);
        }
#pragma unroll
        for (int j2 = 0; j2 < 2; j2++) {
            uint32_t b[4];
            if (!TRANSB) {
                const uint32_t bo =
                    swoff(wn * 32 + j2 * 16 + (lane >> 4) * 8 + (lane & 7),
                          kk * 16 + ((lane >> 3) & 1) * 8);
                ldsm4(b, smem + offB + bo);
            } else {
                const uint32_t bo =
                    swoff(kk * 16 + (lane & 7) + ((lane >> 3) & 1) * 8,
                          wn * 32 + j2 * 16 + (lane >> 4) * 8);
                ldsm4t(b, smem + offB + bo);
            }
#pragma unroll
            for (int im = 0; im < 2; im++) {
                mma16816(acc[im][2 * j2 + 0], aH[im], b[0], b[1]);
                mma16816(acc[im][2 * j2 + 1], aH[im], b[2], b[3]);
            }
#pragma unroll
            for (int im = 0; im < 2; im++) {
                mma16816(acc[im][2 * j2 + 0], aL[im], b[0], b[1]);
                mma16816(acc[im][2 * j2 + 1], aL[im], b[2], b[3]);
            }
        }
    }
}

// ---------------- main kernel ----------------
__global__ void __launch_bounds__(NTH, 1)
sdpa_kernel(const float* __restrict__ Q, const float* __restrict__ K,
            const float* __restrict__ V, const int* __restrict__ mask,
            const float* __restrict__ scalep, float* __restrict__ out) {
    extern __shared__ unsigned char smem[];
    const uint32_t sbase = smem_u32(smem);
    float* rowsum = reinterpret_cast<float*>(smem + OFF_RS);

    const int tid  = threadIdx.x;
    const int lane = tid & 31;
    const int warp = tid >> 5;
    const int wm = warp >> 2;   // 0..3
    const int wn = warp & 3;    // 0..3

    const int bh = blockIdx.x >> 4;       // 0..31
    const int qt = blockIdx.x & 15;
    const int b  = bh >> 4;               // H = 16
    const int qbase = qt * 128;

    const float scale = *scalep;
    const float* Qg = Q + ((size_t)bh * SS + qbase) * DD;
    const float* Kg = K + (size_t)bh * SS * DD;
    const float* Vg = V + (size_t)bh * SS * DD;
    const int*   mb = mask + (size_t)b * SS * SS;
    float* ctx = out + ((size_t)bh * SS + qbase) * DD;
    float* att = out + CTX_ELEMS + ((size_t)bh * SS + qbase) * SS;

    // prologue: stage K(0) chunks 0,1; Q split hi/lo (thread owns 32 floats)
    stage_chunk(sbase, 0, Kg + 0 * 4096, tid);
    stage_chunk(sbase, 1, Kg + 1 * 4096, tid);
    if (tid < 128) rowsum[tid] = 0.f;
#pragma unroll 1
    for (int pass = 0; pass < 4; pass++) {
        const int r = pass * 32 + (tid >> 4);
        const int c = (tid & 15) * 8;
        float4 v0 = *reinterpret_cast<const float4*>(Qg + (size_t)r * DD + c);
        float4 v1 = *reinterpret_cast<const float4*>(Qg + (size_t)r * DD + c + 4);
        uint4 hi, lo;
        split8h(v0, v1, hi, lo);
        const uint32_t off = (uint32_t)(r * 256 + ((((c >> 3) ^ (r & 7))) << 4));
        *reinterpret_cast<uint4*>(smem + OFF_QH + off) = hi;
        *reinterpret_cast<uint4*>(smem + OFF_QL + off) = lo;
    }

    float oacc[2][4][4];
#pragma unroll
    for (int im = 0; im < 2; im++)
#pragma unroll
        for (int j = 0; j < 4; j++)
#pragma unroll
            for (int c = 0; c < 4; c++) oacc[im][j][c] = 0.f;

#pragma unroll 1
    for (int kt = 0; kt < SS / 128; kt++) {
        const float* Kt = Kg + (size_t)kt * 128 * DD;
        const float* Vt = Vg + (size_t)kt * 128 * DD;
        const float* Nt = (kt + 1 < SS / 128) ? Kg + (size_t)(kt + 1) * 128 * DD : Kg;

        __syncthreads();   // bar A: prev PV done reading KV(V)

        conv_chunk(smem, sbase, 0, 0, Kt + 2 * 4096, tid);
        conv_chunk(smem, sbase, 1, 1, Kt + 3 * 4096, tid);
        conv_chunk(smem, sbase, 0, 2, Vt + 0 * 4096, tid);
        conv_chunk(smem, sbase, 1, 3, Vt + 1 * 4096, tid);

        __syncthreads();   // bar B: K tile visible

        // ---- S = Q K^T (Q hi/lo split, K single fp16) ----
        float sacc[2][4][4];
#pragma unroll
        for (int im = 0; im < 2; im++)
#pragma unroll
            for (int j = 0; j < 4; j++)
#pragma unroll
                for (int c = 0; c < 4; c++) sacc[im][j][c] = 0.f;

        gemm_tile<false>(smem, OFF_QH, OFF_QL, OFF_KV, sacc, wm, wn, lane);

        // ---- epilogue: raw exp -> P hi/lo fp16 ----
#pragma unroll
        for (int im = 0; im < 2; im++) {
#pragma unroll
            for (int half = 0; half < 2; half++) {
                const int ql = wm * 32 + im * 16 + (lane >> 2) + half * 8;
#pragma unroll
                for (int jn = 0; jn < 4; jn++) {
                    const int nc = wn * 32 + jn * 8 + (lane & 3) * 2;
                    float e0 = __expf(sacc[im][jn][half * 2 + 0] * scale);
                    float e1 = __expf(sacc[im][jn][half * 2 + 1] * scale);
                    __half h0 = __float2half_rn(e0);
                    __half h1 = __float2half_rn(e1);
                    __half l0 = __float2half_rn(e0 - __half2float(h0));
                    __half l1 = __float2half_rn(e1 - __half2float(h1));
                    const uint32_t po = swoff(ql, nc);
                    *reinterpret_cast<uint32_t*>(smem + OFF_PH + po) = pack2h(h0, h1);
                    *reinterpret_cast<uint32_t*>(smem + OFF_PL + po) = pack2h(l0, l1);
                }
            }
        }

        __syncthreads();   // bar C: P raw visible; S-gemm KV reads done

        conv_chunk(smem, sbase, 0, 0, Vt + 2 * 4096, tid);
        conv_chunk(smem, sbase, 1, 1, Vt + 3 * 4096, tid);
        conv_chunk(smem, sbase, 0, 2, Nt + 0 * 4096, tid);
        conv_chunk(smem, sbase, 1, 3, Nt + 1 * 4096, tid);

        // ---- att phase: warp owns rows warp*8..+7 (coalesced) ----
        {
            const int r0 = warp * 8;
            const int cc = lane * 4;
#pragma unroll
            for (int i = 0; i < 8; i++) {
                const int r = r0 + i;
                const uint32_t po = swoff(r, cc);
                uint2 hp = *reinterpret_cast<const uint2*>(smem + OFF_PH + po);
                uint2 lp = *reinterpret_cast<const uint2*>(smem + OFF_PL + po);
                __half2 h01 = *reinterpret_cast<__half2*>(&hp.x);
                __half2 h23 = *reinterpret_cast<__half2*>(&hp.y);
                __half2 l01 = *reinterpret_cast<__half2*>(&lp.x);
                __half2 l23 = *reinterpret_cast<__half2*>(&lp.y);
                float e0 = __half2float(__low2half(h01)) + __half2float(__low2half(l01));
                float e1 = __half2float(__high2half(h01)) + __half2float(__high2half(l01));
                float e2 = __half2float(__low2half(h23)) + __half2float(__low2half(l23));
                float e3 = __half2float(__high2half(h23)) + __half2float(__high2half(l23));
                int4 mv = *reinterpret_cast<const int4*>(
                    mb + (size_t)(qbase + r) * SS + kt * 128 + cc);
                if (!mv.x) { e0 = 0.f; hp.x &= 0xffff0000u; lp.x &= 0xffff0000u; }
                if (!mv.y) { e1 = 0.f; hp.x &= 0x0000ffffu; lp.x &= 0x0000ffffu; }
                if (!mv.z) { e2 = 0.f; hp.y &= 0xffff0000u; lp.y &= 0xffff0000u; }
                if (!mv.w) { e3 = 0.f; hp.y &= 0x0000ffffu; lp.y &= 0x0000ffffu; }
                *reinterpret_cast<float4*>(att + (size_t)r * SS + kt * 128 + cc) =
                    make_float4(e0, e1, e2, e3);
                *reinterpret_cast<uint2*>(smem + OFF_PH + po) = hp;
                *reinterpret_cast<uint2*>(smem + OFF_PL + po) = lp;
                float s = (e0 + e1) + (e2 + e3);
                s += __shfl_xor_sync(0xffffffff, s, 16);
                s += __shfl_xor_sync(0xffffffff, s, 8);
                s += __shfl_xor_sync(0xffffffff, s, 4);
                s += __shfl_xor_sync(0xffffffff, s, 2);
                s += __shfl_xor_sync(0xffffffff, s, 1);
                if (lane == 0) rowsum[r] += s;
            }
        }

        __syncthreads();   // bar D: V + masked P visible

        // ---- O += P V (P hi/lo split, V single fp16, trans B) ----
        gemm_tile<true>(smem, OFF_PH, OFF_PL, OFF_KV, oacc, wm, wn, lane);
    }

    asm volatile("cp.async.wait_group 0;" ::: "memory");
    __syncthreads();
    if (tid < 128) rowsum[tid] = 1.f / rowsum[tid];
    __syncthreads();

    // ---- write context = O * rnorm ----
#pragma unroll
    for (int im = 0; im < 2; im++)
#pragma unroll
        for (int half = 0; half < 2; half++) {
            const int ql = wm * 32 + im * 16 + (lane >> 2) + half * 8;
            const float rn = rowsum[ql];
            float* crow = ctx + (size_t)ql * DD;
#pragma unroll
            for (int jn = 0; jn < 4; jn++) {
                const int d0 = wn * 32 + jn * 8 + (lane & 3) * 2;
                *reinterpret_cast<float2*>(crow + d0) =
                    make_float2(oacc[im][jn][half * 2 + 0] * rn,
                                oacc[im][jn][half * 2 + 1] * rn);
            }
        }

    // ---- normalize this CTA's attention slice in place ----
    float2* ap = reinterpret_cast<float2*>(att);
#pragma unroll 4
    for (int i = tid; i < 128 * SS / 2; i += NTH) {
        float rn = rowsum[i >> 10];   // 1024 float2 per row
        float2 v = ap[i];
        v.x *= rn;
        v.y *= rn;
        ap[i] = v;
    }
}

// ---------------- launch ----------------
extern "C" void kernel_launch(void* const* d_in, const int* in_sizes, int n_in,
                              void* d_out, int out_size) {
    const float* Q = (const float*)d_in[0];
    const float* K = (const float*)d_in[1];
    const float* V = (const float*)d_in[2];
    const int*   M = (const int*)d_in[3];
    const float* scale = (const float*)d_in[4];
    float* out = (float*)d_out;

    cudaFuncSetAttribute(sdpa_kernel, cudaFuncAttributeMaxDynamicSharedMemorySize,
                         SMEM_SZ);
    sdpa_kernel<<<512, NTH, SMEM_SZ>>>(Q, K, V, M, scale, out);
}

// round 13
// speedup vs baseline: 2.7818x; 1.1919x over previous
#include <cuda_runtime.h>
#include <cuda_fp16.h>
#include <cstdint>

// Problem constants
#define SS 2048
#define DD 128
#define NTH 512
#define CTX_ELEMS ((size_t)2 * 16 * 2048 * 128)   // 8388608

// ---- dynamic smem byte offsets (swizzled buffers, 256 B row pitch) ----
#define OFF_QH  0                  // 128x128 fp16 hi
#define OFF_QL  32768              // 128x128 fp16 lo
#define OFF_KV  65536              // 128x128 fp16 (K then V), single precision
#define OFF_P   98304              // 128x128 fp16 single
#define OFF_STG 131072             // 2 slots x 16384 raw fp32 chunks
#define OFF_RS  163840             // float[128]
#define SMEM_SZ 164352

// ---------------- PTX helpers ----------------
__device__ __forceinline__ uint32_t smem_u32(const void* p) {
    return (uint32_t)__cvta_generic_to_shared(p);
}

// byte offset of fp16 element (r, c) in swizzled 128x128 tile (row = 256 B)
__device__ __forceinline__ uint32_t swoff(int r, int c) {
    return (uint32_t)(r * 256 + ((((c >> 3) ^ (r & 7)) << 4) | ((c & 7) << 1)));
}

__device__ __forceinline__ void ldsm4(uint32_t (&r)[4], const void* p) {
    uint32_t a = smem_u32(p);
    asm volatile("ldmatrix.sync.aligned.m8n8.x4.shared.b16 {%0,%1,%2,%3}, [%4];"
                 : "=r"(r[0]), "=r"(r[1]), "=r"(r[2]), "=r"(r[3]) : "r"(a));
}
__device__ __forceinline__ void ldsm4t(uint32_t (&r)[4], const void* p) {
    uint32_t a = smem_u32(p);
    asm volatile("ldmatrix.sync.aligned.m8n8.x4.trans.shared.b16 {%0,%1,%2,%3}, [%4];"
                 : "=r"(r[0]), "=r"(r[1]), "=r"(r[2]), "=r"(r[3]) : "r"(a));
}
__device__ __forceinline__ void mma16816(float (&c)[4], const uint32_t (&a)[4],
                                         uint32_t b0, uint32_t b1) {
    asm volatile(
        "mma.sync.aligned.m16n8k16.row.col.f32.f16.f16.f32 "
        "{%0,%1,%2,%3},{%4,%5,%6,%7},{%8,%9},{%0,%1,%2,%3};"
        : "+f"(c[0]), "+f"(c[1]), "+f"(c[2]), "+f"(c[3])
        : "r"(a[0]), "r"(a[1]), "r"(a[2]), "r"(a[3]), "r"(b0), "r"(b1));
}
__device__ __forceinline__ uint32_t pack2h(__half a, __half b) {
    __half2 t = __halves2half2(a, b);
    return *reinterpret_cast<uint32_t*>(&t);
}
__device__ __forceinline__ void cpasync16(uint32_t saddr, const void* g) {
    asm volatile("cp.async.cg.shared.global [%0], [%1], 16;"
                 :: "r"(saddr), "l"(g) : "memory");
}

// split 8 fp32 -> fp16 hi + fp16 lo residual
__device__ __forceinline__ void split8h(float4 v0, float4 v1, uint4& hi, uint4& lo) {
    float x[8] = {v0.x, v0.y, v0.z, v0.w, v1.x, v1.y, v1.z, v1.w};
    __half h[8], l[8];
#pragma unroll
    for (int j = 0; j < 8; j++) {
        h[j] = __float2half_rn(x[j]);
        l[j] = __float2half_rn(x[j] - __half2float(h[j]));
    }
    hi = make_uint4(pack2h(h[0], h[1]), pack2h(h[2], h[3]),
                    pack2h(h[4], h[5]), pack2h(h[6], h[7]));
    lo = make_uint4(pack2h(l[0], l[1]), pack2h(l[2], l[3]),
                    pack2h(l[4], l[5]), pack2h(l[6], l[7]));
}
// convert 8 fp32 -> single fp16
__device__ __forceinline__ void cvt8h(float4 v0, float4 v1, uint4& hi) {
    hi = make_uint4(
        pack2h(__float2half_rn(v0.x), __float2half_rn(v0.y)),
        pack2h(__float2half_rn(v0.z), __float2half_rn(v0.w)),
        pack2h(__float2half_rn(v1.x), __float2half_rn(v1.y)),
        pack2h(__float2half_rn(v1.z), __float2half_rn(v1.w)));
}

// stage one 16 KB chunk (32 rows x 128 fp32); thread stages its own 32 B
__device__ __forceinline__ void stage_chunk(uint32_t sbase, int slot,
                                            const float* gsrc, int tid) {
    uint32_t sa = sbase + OFF_STG + slot * 16384 + tid * 32;
    const char* g = reinterpret_cast<const char*>(gsrc) + tid * 32;
    cpasync16(sa, g);
    cpasync16(sa + 16, g + 16);
    asm volatile("cp.async.commit_group;" ::: "memory");
}

// barrier-free: wait own staged chunk, convert rows [ch*32, +32) into KV
// (single fp16), then restage slot with next_gsrc.
__device__ __forceinline__ void conv_chunk(unsigned char* smem, uint32_t sbase,
                                           int slot, int ch,
                                           const float* next_gsrc, int tid) {
    asm volatile("cp.async.wait_group 1;" ::: "memory");
    const float* stg = reinterpret_cast<const float*>(smem + OFF_STG + slot * 16384);
    const int rl = tid >> 4;
    const int c  = (tid & 15) * 8;
    const int r  = ch * 32 + rl;
    float4 v0 = *reinterpret_cast<const float4*>(stg + rl * 128 + c);
    float4 v1 = *reinterpret_cast<const float4*>(stg + rl * 128 + c + 4);
    uint4 hi;
    cvt8h(v0, v1, hi);
    const uint32_t off = (uint32_t)(r * 256 + ((((c >> 3) ^ (r & 7))) << 4));
    *reinterpret_cast<uint4*>(smem + OFF_KV + off) = hi;
    stage_chunk(sbase, slot, next_gsrc, tid);
}

// ---------------- main kernel ----------------
__global__ void __launch_bounds__(NTH, 1)
sdpa_kernel(const float* __restrict__ Q, const float* __restrict__ K,
            const float* __restrict__ V, const int* __restrict__ mask,
            const float* __restrict__ scalep, float* __restrict__ out) {
    extern __shared__ unsigned char smem[];
    const uint32_t sbase = smem_u32(smem);
    float* rowsum = reinterpret_cast<float*>(smem + OFF_RS);

    const int tid  = threadIdx.x;
    const int lane = tid & 31;
    const int warp = tid >> 5;
    const int wm = warp >> 2;   // 0..3
    const int wn = warp & 3;    // 0..3

    const int bh = blockIdx.x >> 4;       // 0..31
    const int qt = blockIdx.x & 15;
    const int b  = bh >> 4;               // H = 16
    const int qbase = qt * 128;

    const float scale = *scalep;
    const float* Qg = Q + ((size_t)bh * SS + qbase) * DD;
    const float* Kg = K + (size_t)bh * SS * DD;
    const float* Vg = V + (size_t)bh * SS * DD;
    const int*   mb = mask + (size_t)b * SS * SS;
    float* ctx = out + ((size_t)bh * SS + qbase) * DD;
    float* att = out + CTX_ELEMS + ((size_t)bh * SS + qbase) * SS;

    // prologue: stage K(0) chunks 0,1; Q split hi/lo (thread owns 32 floats)
    stage_chunk(sbase, 0, Kg + 0 * 4096, tid);
    stage_chunk(sbase, 1, Kg + 1 * 4096, tid);
    if (tid < 128) rowsum[tid] = 0.f;
#pragma unroll 1
    for (int pass = 0; pass < 4; pass++) {
        const int r = pass * 32 + (tid >> 4);
        const int c = (tid & 15) * 8;
        float4 v0 = *reinterpret_cast<const float4*>(Qg + (size_t)r * DD + c);
        float4 v1 = *reinterpret_cast<const float4*>(Qg + (size_t)r * DD + c + 4);
        uint4 hi, lo;
        split8h(v0, v1, hi, lo);
        const uint32_t off = (uint32_t)(r * 256 + ((((c >> 3) ^ (r & 7))) << 4));
        *reinterpret_cast<uint4*>(smem + OFF_QH + off) = hi;
        *reinterpret_cast<uint4*>(smem + OFF_QL + off) = lo;
    }

    float oacc[2][4][4];
#pragma unroll
    for (int im = 0; im < 2; im++)
#pragma unroll
        for (int j = 0; j < 4; j++)
#pragma unroll
            for (int c = 0; c < 4; c++) oacc[im][j][c] = 0.f;

#pragma unroll 1
    for (int kt = 0; kt < SS / 128; kt++) {
        const float* Kt = Kg + (size_t)kt * 128 * DD;
        const float* Vt = Vg + (size_t)kt * 128 * DD;
        const float* Nt = (kt + 1 < SS / 128) ? Kg + (size_t)(kt + 1) * 128 * DD : Kg;

        __syncthreads();   // bar A: prev PV done reading KV(V)

        conv_chunk(smem, sbase, 0, 0, Kt + 2 * 4096, tid);
        conv_chunk(smem, sbase, 1, 1, Kt + 3 * 4096, tid);
        conv_chunk(smem, sbase, 0, 2, Vt + 0 * 4096, tid);
        conv_chunk(smem, sbase, 1, 3, Vt + 1 * 4096, tid);

        __syncthreads();   // bar B: K tile visible

        // ---- S = Q K^T (Q hi/lo split, K single fp16: 2 products) ----
        float sacc[2][4][4];
#pragma unroll
        for (int im = 0; im < 2; im++)
#pragma unroll
            for (int j = 0; j < 4; j++)
#pragma unroll
                for (int c = 0; c < 4; c++) sacc[im][j][c] = 0.f;

#pragma unroll 1
        for (int kk = 0; kk < 8; kk++) {
            uint32_t aH[2][4], aL[2][4];
#pragma unroll
            for (int im = 0; im < 2; im++) {
                const uint32_t ao = swoff(wm * 32 + im * 16 + (lane & 15),
                                          kk * 16 + (lane >> 4) * 8);
                ldsm4(aH[im], smem + OFF_QH + ao);
                ldsm4(aL[im], smem + OFF_QL + ao);
            }
#pragma unroll
            for (int j2 = 0; j2 < 2; j2++) {
                const uint32_t bo =
                    swoff(wn * 32 + j2 * 16 + (lane >> 4) * 8 + (lane & 7),
                          kk * 16 + ((lane >> 3) & 1) * 8);
                uint32_t bb[4];
                ldsm4(bb, smem + OFF_KV + bo);
#pragma unroll
                for (int im = 0; im < 2; im++) {
                    mma16816(sacc[im][2 * j2 + 0], aH[im], bb[0], bb[1]);
                    mma16816(sacc[im][2 * j2 + 1], aH[im], bb[2], bb[3]);
                }
#pragma unroll
                for (int im = 0; im < 2; im++) {
                    mma16816(sacc[im][2 * j2 + 0], aL[im], bb[0], bb[1]);
                    mma16816(sacc[im][2 * j2 + 1], aL[im], bb[2], bb[3]);
                }
            }
        }

        // ---- epilogue: raw exp -> P single fp16 ----
#pragma unroll
        for (int im = 0; im < 2; im++) {
#pragma unroll
            for (int half = 0; half < 2; half++) {
                const int ql = wm * 32 + im * 16 + (lane >> 2) + half * 8;
#pragma unroll
                for (int jn = 0; jn < 4; jn++) {
                    const int nc = wn * 32 + jn * 8 + (lane & 3) * 2;
                    float e0 = __expf(sacc[im][jn][half * 2 + 0] * scale);
                    float e1 = __expf(sacc[im][jn][half * 2 + 1] * scale);
                    const uint32_t po = swoff(ql, nc);
                    *reinterpret_cast<uint32_t*>(smem + OFF_P + po) =
                        pack2h(__float2half_rn(e0), __float2half_rn(e1));
                }
            }
        }

        __syncthreads();   // bar C: P raw visible; S-gemm KV reads done

        conv_chunk(smem, sbase, 0, 0, Vt + 2 * 4096, tid);
        conv_chunk(smem, sbase, 1, 1, Vt + 3 * 4096, tid);
        conv_chunk(smem, sbase, 0, 2, Nt + 0 * 4096, tid);
        conv_chunk(smem, sbase, 1, 3, Nt + 1 * 4096, tid);

        // ---- att phase: warp owns rows warp*8..+7 (coalesced) ----
        {
            const int r0 = warp * 8;
            const int cc = lane * 4;
#pragma unroll
            for (int i = 0; i < 8; i++) {
                const int r = r0 + i;
                const uint32_t po = swoff(r, cc);
                uint2 hp = *reinterpret_cast<const uint2*>(smem + OFF_P + po);
                __half2 h01 = *reinterpret_cast<__half2*>(&hp.x);
                __half2 h23 = *reinterpret_cast<__half2*>(&hp.y);
                float e0 = __half2float(__low2half(h01));
                float e1 = __half2float(__high2half(h01));
                float e2 = __half2float(__low2half(h23));
                float e3 = __half2float(__high2half(h23));
                int4 mv = *reinterpret_cast<const int4*>(
                    mb + (size_t)(qbase + r) * SS + kt * 128 + cc);
                if (!mv.x) { e0 = 0.f; hp.x &= 0xffff0000u; }
                if (!mv.y) { e1 = 0.f; hp.x &= 0x0000ffffu; }
                if (!mv.z) { e2 = 0.f; hp.y &= 0xffff0000u; }
                if (!mv.w) { e3 = 0.f; hp.y &= 0x0000ffffu; }
                *reinterpret_cast<float4*>(att + (size_t)r * SS + kt * 128 + cc) =
                    make_float4(e0, e1, e2, e3);
                *reinterpret_cast<uint2*>(smem + OFF_P + po) = hp;
                float s = (e0 + e1) + (e2 + e3);
                s += __shfl_xor_sync(0xffffffff, s, 16);
                s += __shfl_xor_sync(0xffffffff, s, 8);
                s += __shfl_xor_sync(0xffffffff, s, 4);
                s += __shfl_xor_sync(0xffffffff, s, 2);
                s += __shfl_xor_sync(0xffffffff, s, 1);
                if (lane == 0) rowsum[r] += s;
            }
        }

        __syncthreads();   // bar D: V + masked P visible

        // ---- O += P V (P single, V single: 1 product, trans B) ----
#pragma unroll 1
        for (int kk = 0; kk < 8; kk++) {
            uint32_t a[2][4];
#pragma unroll
            for (int im = 0; im < 2; im++) {
                const uint32_t ao = swoff(wm * 32 + im * 16 + (lane & 15),
                                          kk * 16 + (lane >> 4) * 8);
                ldsm4(a[im], smem + OFF_P + ao);
            }
#pragma unroll
            for (int j2 = 0; j2 < 2; j2++) {
                const uint32_t bo =
                    swoff(kk * 16 + (lane & 7) + ((lane >> 3) & 1) * 8,
                          wn * 32 + j2 * 16 + (lane >> 4) * 8);
                uint32_t bb[4];
                ldsm4t(bb, smem + OFF_KV + bo);
#pragma unroll
                for (int im = 0; im < 2; im++) {
                    mma16816(oacc[im][2 * j2 + 0], a[im], bb[0], bb[1]);
                    mma16816(oacc[im][2 * j2 + 1], a[im], bb[2], bb[3]);
                }
            }
        }
    }

    asm volatile("cp.async.wait_group 0;" ::: "memory");
    __syncthreads();
    if (tid < 128) rowsum[tid] = 1.f / rowsum[tid];
    __syncthreads();

    // ---- write context = O * rnorm ----
#pragma unroll
    for (int im = 0; im < 2; im++)
#pragma unroll
        for (int half = 0; half < 2; half++) {
            const int ql = wm * 32 + im * 16 + (lane >> 2) + half * 8;
            const float rn = rowsum[ql];
            float* crow = ctx + (size_t)ql * DD;
#pragma unroll
            for (int jn = 0; jn < 4; jn++) {
                const int d0 = wn * 32 + jn * 8 + (lane & 3) * 2;
                *reinterpret_cast<float2*>(crow + d0) =
                    make_float2(oacc[im][jn][half * 2 + 0] * rn,
                                oacc[im][jn][half * 2 + 1] * rn);
            }
        }

    // ---- normalize this CTA's attention slice in place (float4) ----
    float4* ap = reinterpret_cast<float4*>(att);
#pragma unroll 4
    for (int i = tid; i < 128 * SS / 4; i += NTH) {
        float rn = rowsum[i >> 9];   // 512 float4 per row
        float4 v = ap[i];
        v.x *= rn;
        v.y *= rn;
        v.z *= rn;
        v.w *= rn;
        ap[i] = v;
    }
}

// ---------------- launch ----------------
extern "C" void kernel_launch(void* const* d_in, const int* in_sizes, int n_in,
                              void* d_out, int out_size) {
    const float* Q = (const float*)d_in[0];
    const float* K = (const float*)d_in[1];
    const float* V = (const float*)d_in[2];
    const int*   M = (const int*)d_in[3];
    const float* scale = (const float*)d_in[4];
    float* out = (float*)d_out;

    cudaFuncSetAttribute(sdpa_kernel, cudaFuncAttributeMaxDynamicSharedMemorySize,
                         SMEM_SZ);
    sdpa_kernel<<<512, NTH, SMEM_SZ>>>(Q, K, V, M, scale, out);
}

// round 14
// speedup vs baseline: 3.0034x; 1.0797x over previous
#include <cuda_runtime.h>
#include <cuda_fp16.h>
#include <cstdint>

// Problem constants
#define SS 2048
#define DD 128
#define NTH 512
#define CTX_ELEMS ((size_t)2 * 16 * 2048 * 128)   // 8388608

// ---- dynamic smem byte offsets (swizzled buffers, 256 B row pitch) ----
#define OFF_Q   0                  // 128x128 fp16 single
#define OFF_KV  32768              // 128x128 fp16 (K then V), single
#define OFF_P   65536              // 128x128 fp16 single
#define OFF_STG 98304              // 2 slots x 16384 raw fp32 chunks
#define OFF_RS  131072             // float[128]
#define SMEM_SZ 131584

// ---------------- PTX helpers ----------------
__device__ __forceinline__ uint32_t smem_u32(const void* p) {
    return (uint32_t)__cvta_generic_to_shared(p);
}

// byte offset of fp16 element (r, c) in swizzled 128x128 tile (row = 256 B)
__device__ __forceinline__ uint32_t swoff(int r, int c) {
    return (uint32_t)(r * 256 + ((((c >> 3) ^ (r & 7)) << 4) | ((c & 7) << 1)));
}

__device__ __forceinline__ void ldsm4(uint32_t (&r)[4], const void* p) {
    uint32_t a = smem_u32(p);
    asm volatile("ldmatrix.sync.aligned.m8n8.x4.shared.b16 {%0,%1,%2,%3}, [%4];"
                 : "=r"(r[0]), "=r"(r[1]), "=r"(r[2]), "=r"(r[3]) : "r"(a));
}
__device__ __forceinline__ void ldsm4t(uint32_t (&r)[4], const void* p) {
    uint32_t a = smem_u32(p);
    asm volatile("ldmatrix.sync.aligned.m8n8.x4.trans.shared.b16 {%0,%1,%2,%3}, [%4];"
                 : "=r"(r[0]), "=r"(r[1]), "=r"(r[2]), "=r"(r[3]) : "r"(a));
}
__device__ __forceinline__ void mma16816(float (&c)[4], const uint32_t (&a)[4],
                                         uint32_t b0, uint32_t b1) {
    asm volatile(
        "mma.sync.aligned.m16n8k16.row.col.f32.f16.f16.f32 "
        "{%0,%1,%2,%3},{%4,%5,%6,%7},{%8,%9},{%0,%1,%2,%3};"
        : "+f"(c[0]), "+f"(c[1]), "+f"(c[2]), "+f"(c[3])
        : "r"(a[0]), "r"(a[1]), "r"(a[2]), "r"(a[3]), "r"(b0), "r"(b1));
}
__device__ __forceinline__ uint32_t pack2h(__half a, __half b) {
    __half2 t = __halves2half2(a, b);
    return *reinterpret_cast<uint32_t*>(&t);
}
__device__ __forceinline__ void cpasync16(uint32_t saddr, const void* g) {
    asm volatile("cp.async.cg.shared.global [%0], [%1], 16;"
                 :: "r"(saddr), "l"(g) : "memory");
}

// convert 8 fp32 -> single fp16
__device__ __forceinline__ void cvt8h(float4 v0, float4 v1, uint4& hi) {
    hi = make_uint4(
        pack2h(__float2half_rn(v0.x), __float2half_rn(v0.y)),
        pack2h(__float2half_rn(v0.z), __float2half_rn(v0.w)),
        pack2h(__float2half_rn(v1.x), __float2half_rn(v1.y)),
        pack2h(__float2half_rn(v1.z), __float2half_rn(v1.w)));
}

// stage one 16 KB chunk (32 rows x 128 fp32); thread stages its own 32 B
__device__ __forceinline__ void stage_chunk(uint32_t sbase, int slot,
                                            const float* gsrc, int tid) {
    uint32_t sa = sbase + OFF_STG + slot * 16384 + tid * 32;
    const char* g = reinterpret_cast<const char*>(gsrc) + tid * 32;
    cpasync16(sa, g);
    cpasync16(sa + 16, g + 16);
    asm volatile("cp.async.commit_group;" ::: "memory");
}

// barrier-free: wait own staged chunk, convert rows [ch*32, +32) into KV
// (single fp16), then restage slot with next_gsrc.
__device__ __forceinline__ void conv_chunk(unsigned char* smem, uint32_t sbase,
                                           int slot, int ch,
                                           const float* next_gsrc, int tid) {
    asm volatile("cp.async.wait_group 1;" ::: "memory");
    const float* stg = reinterpret_cast<const float*>(smem + OFF_STG + slot * 16384);
    const int rl = tid >> 4;
    const int c  = (tid & 15) * 8;
    const int r  = ch * 32 + rl;
    float4 v0 = *reinterpret_cast<const float4*>(stg + rl * 128 + c);
    float4 v1 = *reinterpret_cast<const float4*>(stg + rl * 128 + c + 4);
    uint4 hi;
    cvt8h(v0, v1, hi);
    const uint32_t off = (uint32_t)(r * 256 + ((((c >> 3) ^ (r & 7))) << 4));
    *reinterpret_cast<uint4*>(smem + OFF_KV + off) = hi;
    stage_chunk(sbase, slot, next_gsrc, tid);
}

// ---------------- main kernel ----------------
__global__ void __launch_bounds__(NTH, 1)
sdpa_kernel(const float* __restrict__ Q, const float* __restrict__ K,
            const float* __restrict__ V, const int* __restrict__ mask,
            const float* __restrict__ scalep, float* __restrict__ out) {
    extern __shared__ unsigned char smem[];
    const uint32_t sbase = smem_u32(smem);
    float* rowsum = reinterpret_cast<float*>(smem + OFF_RS);

    const int tid  = threadIdx.x;
    const int lane = tid & 31;
    const int warp = tid >> 5;
    const int wm = warp >> 2;   // 0..3
    const int wn = warp & 3;    // 0..3

    const int bh = blockIdx.x >> 4;       // 0..31
    const int qt = blockIdx.x & 15;
    const int b  = bh >> 4;               // H = 16
    const int qbase = qt * 128;

    const float scale = *scalep;
    const float* Qg = Q + ((size_t)bh * SS + qbase) * DD;
    const float* Kg = K + (size_t)bh * SS * DD;
    const float* Vg = V + (size_t)bh * SS * DD;
    const int*   mb = mask + (size_t)b * SS * SS;
    float* ctx = out + ((size_t)bh * SS + qbase) * DD;
    float* att = out + CTX_ELEMS + ((size_t)bh * SS + qbase) * SS;

    // prologue: stage K(0) chunks 0,1; Q -> single fp16 (thread owns 32 floats)
    stage_chunk(sbase, 0, Kg + 0 * 4096, tid);
    stage_chunk(sbase, 1, Kg + 1 * 4096, tid);
    if (tid < 128) rowsum[tid] = 0.f;
#pragma unroll 1
    for (int pass = 0; pass < 4; pass++) {
        const int r = pass * 32 + (tid >> 4);
        const int c = (tid & 15) * 8;
        float4 v0 = *reinterpret_cast<const float4*>(Qg + (size_t)r * DD + c);
        float4 v1 = *reinterpret_cast<const float4*>(Qg + (size_t)r * DD + c + 4);
        uint4 hi;
        cvt8h(v0, v1, hi);
        const uint32_t off = (uint32_t)(r * 256 + ((((c >> 3) ^ (r & 7))) << 4));
        *reinterpret_cast<uint4*>(smem + OFF_Q + off) = hi;
    }

    float oacc[2][4][4];
#pragma unroll
    for (int im = 0; im < 2; im++)
#pragma unroll
        for (int j = 0; j < 4; j++)
#pragma unroll
            for (int c = 0; c < 4; c++) oacc[im][j][c] = 0.f;

#pragma unroll 1
    for (int kt = 0; kt < SS / 128; kt++) {
        const float* Kt = Kg + (size_t)kt * 128 * DD;
        const float* Vt = Vg + (size_t)kt * 128 * DD;
        const float* Nt = (kt + 1 < SS / 128) ? Kg + (size_t)(kt + 1) * 128 * DD : Kg;

        __syncthreads();   // bar A: prev PV done reading KV(V)

        conv_chunk(smem, sbase, 0, 0, Kt + 2 * 4096, tid);
        conv_chunk(smem, sbase, 1, 1, Kt + 3 * 4096, tid);
        conv_chunk(smem, sbase, 0, 2, Vt + 0 * 4096, tid);
        conv_chunk(smem, sbase, 1, 3, Vt + 1 * 4096, tid);

        __syncthreads();   // bar B: K tile visible

        // ---- S = Q K^T (single fp16 x single fp16) ----
        float sacc[2][4][4];
#pragma unroll
        for (int im = 0; im < 2; im++)
#pragma unroll
            for (int j = 0; j < 4; j++)
#pragma unroll
                for (int c = 0; c < 4; c++) sacc[im][j][c] = 0.f;

#pragma unroll 1
        for (int kk = 0; kk < 8; kk++) {
            uint32_t a[2][4];
#pragma unroll
            for (int im = 0; im < 2; im++) {
                const uint32_t ao = swoff(wm * 32 + im * 16 + (lane & 15),
                                          kk * 16 + (lane >> 4) * 8);
                ldsm4(a[im], smem + OFF_Q + ao);
            }
#pragma unroll
            for (int j2 = 0; j2 < 2; j2++) {
                const uint32_t bo =
                    swoff(wn * 32 + j2 * 16 + (lane >> 4) * 8 + (lane & 7),
                          kk * 16 + ((lane >> 3) & 1) * 8);
                uint32_t bb[4];
                ldsm4(bb, smem + OFF_KV + bo);
#pragma unroll
                for (int im = 0; im < 2; im++) {
                    mma16816(sacc[im][2 * j2 + 0], a[im], bb[0], bb[1]);
                    mma16816(sacc[im][2 * j2 + 1], a[im], bb[2], bb[3]);
                }
            }
        }

        // ---- epilogue: raw exp -> P single fp16 ----
#pragma unroll
        for (int im = 0; im < 2; im++) {
#pragma unroll
            for (int half = 0; half < 2; half++) {
                const int ql = wm * 32 + im * 16 + (lane >> 2) + half * 8;
#pragma unroll
                for (int jn = 0; jn < 4; jn++) {
                    const int nc = wn * 32 + jn * 8 + (lane & 3) * 2;
                    float e0 = __expf(sacc[im][jn][half * 2 + 0] * scale);
                    float e1 = __expf(sacc[im][jn][half * 2 + 1] * scale);
                    const uint32_t po = swoff(ql, nc);
                    *reinterpret_cast<uint32_t*>(smem + OFF_P + po) =
                        pack2h(__float2half_rn(e0), __float2half_rn(e1));
                }
            }
        }

        __syncthreads();   // bar C: P raw visible; S-gemm KV reads done

        conv_chunk(smem, sbase, 0, 0, Vt + 2 * 4096, tid);
        conv_chunk(smem, sbase, 1, 1, Vt + 3 * 4096, tid);
        conv_chunk(smem, sbase, 0, 2, Nt + 0 * 4096, tid);
        conv_chunk(smem, sbase, 1, 3, Nt + 1 * 4096, tid);

        // ---- att phase: warp owns rows warp*8..+7 (coalesced) ----
        {
            const int r0 = warp * 8;
            const int cc = lane * 4;
#pragma unroll
            for (int i = 0; i < 8; i++) {
                const int r = r0 + i;
                const uint32_t po = swoff(r, cc);
                uint2 hp = *reinterpret_cast<const uint2*>(smem + OFF_P + po);
                __half2 h01 = *reinterpret_cast<__half2*>(&hp.x);
                __half2 h23 = *reinterpret_cast<__half2*>(&hp.y);
                float e0 = __half2float(__low2half(h01));
                float e1 = __half2float(__high2half(h01));
                float e2 = __half2float(__low2half(h23));
                float e3 = __half2float(__high2half(h23));
                int4 mv = *reinterpret_cast<const int4*>(
                    mb + (size_t)(qbase + r) * SS + kt * 128 + cc);
                if (!mv.x) { e0 = 0.f; hp.x &= 0xffff0000u; }
                if (!mv.y) { e1 = 0.f; hp.x &= 0x0000ffffu; }
                if (!mv.z) { e2 = 0.f; hp.y &= 0xffff0000u; }
                if (!mv.w) { e3 = 0.f; hp.y &= 0x0000ffffu; }
                *reinterpret_cast<float4*>(att + (size_t)r * SS + kt * 128 + cc) =
                    make_float4(e0, e1, e2, e3);
                *reinterpret_cast<uint2*>(smem + OFF_P + po) = hp;
                float s = (e0 + e1) + (e2 + e3);
                s += __shfl_xor_sync(0xffffffff, s, 16);
                s += __shfl_xor_sync(0xffffffff, s, 8);
                s += __shfl_xor_sync(0xffffffff, s, 4);
                s += __shfl_xor_sync(0xffffffff, s, 2);
                s += __shfl_xor_sync(0xffffffff, s, 1);
                if (lane == 0) rowsum[r] += s;
            }
        }

        __syncthreads();   // bar D: V + masked P visible

        // ---- O += P V (single x single, trans B) ----
#pragma unroll 1
        for (int kk = 0; kk < 8; kk++) {
            uint32_t a[2][4];
#pragma unroll
            for (int im = 0; im < 2; im++) {
                const uint32_t ao = swoff(wm * 32 + im * 16 + (lane & 15),
                                          kk * 16 + (lane >> 4) * 8);
                ldsm4(a[im], smem + OFF_P + ao);
            }
#pragma unroll
            for (int j2 = 0; j2 < 2; j2++) {
                const uint32_t bo =
                    swoff(kk * 16 + (lane & 7) + ((lane >> 3) & 1) * 8,
                          wn * 32 + j2 * 16 + (lane >> 4) * 8);
                uint32_t bb[4];
                ldsm4t(bb, smem + OFF_KV + bo);
#pragma unroll
                for (int im = 0; im < 2; im++) {
                    mma16816(oacc[im][2 * j2 + 0], a[im], bb[0], bb[1]);
                    mma16816(oacc[im][2 * j2 + 1], a[im], bb[2], bb[3]);
                }
            }
        }
    }

    asm volatile("cp.async.wait_group 0;" ::: "memory");
    __syncthreads();
    if (tid < 128) rowsum[tid] = 1.f / rowsum[tid];
    __syncthreads();

    // ---- write context = O * rnorm ----
#pragma unroll
    for (int im = 0; im < 2; im++)
#pragma unroll
        for (int half = 0; half < 2; half++) {
            const int ql = wm * 32 + im * 16 + (lane >> 2) + half * 8;
            const float rn = rowsum[ql];
            float* crow = ctx + (size_t)ql * DD;
#pragma unroll
            for (int jn = 0; jn < 4; jn++) {
                const int d0 = wn * 32 + jn * 8 + (lane & 3) * 2;
                *reinterpret_cast<float2*>(crow + d0) =
                    make_float2(oacc[im][jn][half * 2 + 0] * rn,
                                oacc[im][jn][half * 2 + 1] * rn);
            }
        }

    // ---- normalize this CTA's attention slice in place (float4) ----
    float4* ap = reinterpret_cast<float4*>(att);
#pragma unroll 4
    for (int i = tid; i < 128 * SS / 4; i += NTH) {
        float rn = rowsum[i >> 9];   // 512 float4 per row
        float4 v = ap[i];
        v.x *= rn;
        v.y *= rn;
        v.z *= rn;
        v.w *= rn;
        ap[i] = v;
    }
}

// ---------------- launch ----------------
extern "C" void kernel_launch(void* const* d_in, const int* in_sizes, int n_in,
                              void* d_out, int out_size) {
    const float* Q = (const float*)d_in[0];
    const float* K = (const float*)d_in[1];
    const float* V = (const float*)d_in[2];
    const int*   M = (const int*)d_in[3];
    const float* scale = (const float*)d_in[4];
    float* out = (float*)d_out;

    cudaFuncSetAttribute(sdpa_kernel, cudaFuncAttributeMaxDynamicSharedMemorySize,
                         SMEM_SZ);
    sdpa_kernel<<<512, NTH, SMEM_SZ>>>(Q, K, V, M, scale, out);
}

// round 15
// speedup vs baseline: 3.1476x; 1.0480x over previous
#include <cuda_runtime.h>
#include <cuda_fp16.h>
#include <cstdint>

// Problem constants
#define SS 2048
#define DD 128
#define NTH 512
#define CTX_ELEMS ((size_t)2 * 16 * 2048 * 128)   // 8388608

// ---- dynamic smem byte offsets (swizzled buffers, 256 B row pitch) ----
#define OFF_Q   0                  // 128x128 fp16 single
#define OFF_KV  32768              // 128x128 fp16 (K then V), single
#define OFF_P   65536              // 128x128 fp16 single (masked)
#define OFF_STG 98304              // 2 slots x 16384 raw fp32 chunks
#define OFF_RS  131072             // float[128]
#define SMEM_SZ 131584

// ---------------- PTX helpers ----------------
__device__ __forceinline__ uint32_t smem_u32(const void* p) {
    return (uint32_t)__cvta_generic_to_shared(p);
}

// byte offset of fp16 element (r, c) in swizzled 128x128 tile (row = 256 B)
__device__ __forceinline__ uint32_t swoff(int r, int c) {
    return (uint32_t)(r * 256 + ((((c >> 3) ^ (r & 7)) << 4) | ((c & 7) << 1)));
}

__device__ __forceinline__ void ldsm4(uint32_t (&r)[4], const void* p) {
    uint32_t a = smem_u32(p);
    asm volatile("ldmatrix.sync.aligned.m8n8.x4.shared.b16 {%0,%1,%2,%3}, [%4];"
                 : "=r"(r[0]), "=r"(r[1]), "=r"(r[2]), "=r"(r[3]) : "r"(a));
}
__device__ __forceinline__ void ldsm4t(uint32_t (&r)[4], const void* p) {
    uint32_t a = smem_u32(p);
    asm volatile("ldmatrix.sync.aligned.m8n8.x4.trans.shared.b16 {%0,%1,%2,%3}, [%4];"
                 : "=r"(r[0]), "=r"(r[1]), "=r"(r[2]), "=r"(r[3]) : "r"(a));
}
__device__ __forceinline__ void mma16816(float (&c)[4], const uint32_t (&a)[4],
                                         uint32_t b0, uint32_t b1) {
    asm volatile(
        "mma.sync.aligned.m16n8k16.row.col.f32.f16.f16.f32 "
        "{%0,%1,%2,%3},{%4,%5,%6,%7},{%8,%9},{%0,%1,%2,%3};"
        : "+f"(c[0]), "+f"(c[1]), "+f"(c[2]), "+f"(c[3])
        : "r"(a[0]), "r"(a[1]), "r"(a[2]), "r"(a[3]), "r"(b0), "r"(b1));
}
__device__ __forceinline__ uint32_t pack2h(__half a, __half b) {
    __half2 t = __halves2half2(a, b);
    return *reinterpret_cast<uint32_t*>(&t);
}
__device__ __forceinline__ void cpasync16(uint32_t saddr, const void* g) {
    asm volatile("cp.async.cg.shared.global [%0], [%1], 16;"
                 :: "r"(saddr), "l"(g) : "memory");
}

// convert 8 fp32 -> single fp16
__device__ __forceinline__ void cvt8h(float4 v0, float4 v1, uint4& hi) {
    hi = make_uint4(
        pack2h(__float2half_rn(v0.x), __float2half_rn(v0.y)),
        pack2h(__float2half_rn(v0.z), __float2half_rn(v0.w)),
        pack2h(__float2half_rn(v1.x), __float2half_rn(v1.y)),
        pack2h(__float2half_rn(v1.z), __float2half_rn(v1.w)));
}

// stage one 16 KB chunk (32 rows x 128 fp32); thread stages its own 32 B
__device__ __forceinline__ void stage_chunk(uint32_t sbase, int slot,
                                            const float* gsrc, int tid) {
    uint32_t sa = sbase + OFF_STG + slot * 16384 + tid * 32;
    const char* g = reinterpret_cast<const char*>(gsrc) + tid * 32;
    cpasync16(sa, g);
    cpasync16(sa + 16, g + 16);
    asm volatile("cp.async.commit_group;" ::: "memory");
}

// barrier-free: wait own staged chunk, convert rows [ch*32, +32) into KV
// (single fp16), then restage slot with next_gsrc.
__device__ __forceinline__ void conv_chunk(unsigned char* smem, uint32_t sbase,
                                           int slot, int ch,
                                           const float* next_gsrc, int tid) {
    asm volatile("cp.async.wait_group 1;" ::: "memory");
    const float* stg = reinterpret_cast<const float*>(smem + OFF_STG + slot * 16384);
    const int rl = tid >> 4;
    const int c  = (tid & 15) * 8;
    const int r  = ch * 32 + rl;
    float4 v0 = *reinterpret_cast<const float4*>(stg + rl * 128 + c);
    float4 v1 = *reinterpret_cast<const float4*>(stg + rl * 128 + c + 4);
    uint4 hi;
    cvt8h(v0, v1, hi);
    const uint32_t off = (uint32_t)(r * 256 + ((((c >> 3) ^ (r & 7))) << 4));
    *reinterpret_cast<uint4*>(smem + OFF_KV + off) = hi;
    stage_chunk(sbase, slot, next_gsrc, tid);
}

// ---------------- main kernel ----------------
__global__ void __launch_bounds__(NTH, 1)
sdpa_kernel(const float* __restrict__ Q, const float* __restrict__ K,
            const float* __restrict__ V, const int* __restrict__ mask,
            const float* __restrict__ scalep, float* __restrict__ out) {
    extern __shared__ unsigned char smem[];
    const uint32_t sbase = smem_u32(smem);
    float* rowsum = reinterpret_cast<float*>(smem + OFF_RS);

    const int tid  = threadIdx.x;
    const int lane = tid & 31;
    const int warp = tid >> 5;
    const int wm = warp >> 2;   // 0..3
    const int wn = warp & 3;    // 0..3

    const int bh = blockIdx.x >> 4;       // 0..31
    const int qt = blockIdx.x & 15;
    const int b  = bh >> 4;               // H = 16
    const int qbase = qt * 128;

    const float scale = *scalep;
    const float* Qg = Q + ((size_t)bh * SS + qbase) * DD;
    const float* Kg = K + (size_t)bh * SS * DD;
    const float* Vg = V + (size_t)bh * SS * DD;
    const int*   mb = mask + (size_t)b * SS * SS;
    float* ctx = out + ((size_t)bh * SS + qbase) * DD;
    float* att = out + CTX_ELEMS + ((size_t)bh * SS + qbase) * SS;

    // prologue: stage K(0) chunks 0,1; Q -> single fp16 (thread owns 32 floats)
    stage_chunk(sbase, 0, Kg + 0 * 4096, tid);
    stage_chunk(sbase, 1, Kg + 1 * 4096, tid);
    if (tid < 128) rowsum[tid] = 0.f;
#pragma unroll 1
    for (int pass = 0; pass < 4; pass++) {
        const int r = pass * 32 + (tid >> 4);
        const int c = (tid & 15) * 8;
        float4 v0 = *reinterpret_cast<const float4*>(Qg + (size_t)r * DD + c);
        float4 v1 = *reinterpret_cast<const float4*>(Qg + (size_t)r * DD + c + 4);
        uint4 hi;
        cvt8h(v0, v1, hi);
        const uint32_t off = (uint32_t)(r * 256 + ((((c >> 3) ^ (r & 7))) << 4));
        *reinterpret_cast<uint4*>(smem + OFF_Q + off) = hi;
    }

    float oacc[2][4][4];
#pragma unroll
    for (int im = 0; im < 2; im++)
#pragma unroll
        for (int j = 0; j < 4; j++)
#pragma unroll
            for (int c = 0; c < 4; c++) oacc[im][j][c] = 0.f;

    // per-thread rowsum partials, accumulated across all k-tiles
    float rsacc[2][2] = {{0.f, 0.f}, {0.f, 0.f}};

#pragma unroll 1
    for (int kt = 0; kt < SS / 128; kt++) {
        const float* Kt = Kg + (size_t)kt * 128 * DD;
        const float* Vt = Vg + (size_t)kt * 128 * DD;
        const float* Nt = (kt + 1 < SS / 128) ? Kg + (size_t)(kt + 1) * 128 * DD : Kg;

        __syncthreads();   // bar A: prev PV done reading KV(V)

        conv_chunk(smem, sbase, 0, 0, Kt + 2 * 4096, tid);
        conv_chunk(smem, sbase, 1, 1, Kt + 3 * 4096, tid);
        conv_chunk(smem, sbase, 0, 2, Vt + 0 * 4096, tid);
        conv_chunk(smem, sbase, 1, 3, Vt + 1 * 4096, tid);

        __syncthreads();   // bar B: K tile visible

        // ---- S = Q K^T (single fp16 x single fp16) ----
        float sacc[2][4][4];
#pragma unroll
        for (int im = 0; im < 2; im++)
#pragma unroll
            for (int j = 0; j < 4; j++)
#pragma unroll
                for (int c = 0; c < 4; c++) sacc[im][j][c] = 0.f;

#pragma unroll 1
        for (int kk = 0; kk < 8; kk++) {
            uint32_t a[2][4];
#pragma unroll
            for (int im = 0; im < 2; im++) {
                const uint32_t ao = swoff(wm * 32 + im * 16 + (lane & 15),
                                          kk * 16 + (lane >> 4) * 8);
                ldsm4(a[im], smem + OFF_Q + ao);
            }
#pragma unroll
            for (int j2 = 0; j2 < 2; j2++) {
                const uint32_t bo =
                    swoff(wn * 32 + j2 * 16 + (lane >> 4) * 8 + (lane & 7),
                          kk * 16 + ((lane >> 3) & 1) * 8);
                uint32_t bb[4];
                ldsm4(bb, smem + OFF_KV + bo);
#pragma unroll
                for (int im = 0; im < 2; im++) {
                    mma16816(sacc[im][2 * j2 + 0], a[im], bb[0], bb[1]);
                    mma16816(sacc[im][2 * j2 + 1], a[im], bb[2], bb[3]);
                }
            }
        }

        // ---- fused epilogue: mask + exp + att write + masked P store ----
#pragma unroll
        for (int im = 0; im < 2; im++) {
#pragma unroll
            for (int half = 0; half < 2; half++) {
                const int ql = wm * 32 + im * 16 + (lane >> 2) + half * 8;
                const int* mrow = mb + (size_t)(qbase + ql) * SS + kt * 128;
                float* arow = att + (size_t)ql * SS + kt * 128;
                int2 mv[4];
#pragma unroll
                for (int jn = 0; jn < 4; jn++)
                    mv[jn] = *reinterpret_cast<const int2*>(
                        mrow + wn * 32 + jn * 8 + (lane & 3) * 2);
                float rs = 0.f;
#pragma unroll
                for (int jn = 0; jn < 4; jn++) {
                    const int nc = wn * 32 + jn * 8 + (lane & 3) * 2;
                    float e0 = mv[jn].x ? __expf(sacc[im][jn][half * 2 + 0] * scale) : 0.f;
                    float e1 = mv[jn].y ? __expf(sacc[im][jn][half * 2 + 1] * scale) : 0.f;
                    *reinterpret_cast<float2*>(arow + nc) = make_float2(e0, e1);
                    rs += e0 + e1;
                    const uint32_t po = swoff(ql, nc);
                    *reinterpret_cast<uint32_t*>(smem + OFF_P + po) =
                        pack2h(__float2half_rn(e0), __float2half_rn(e1));
                }
                rsacc[im][half] += rs;
            }
        }

        __syncthreads();   // bar C: P visible; S-gemm KV reads done

        conv_chunk(smem, sbase, 0, 0, Vt + 2 * 4096, tid);
        conv_chunk(smem, sbase, 1, 1, Vt + 3 * 4096, tid);
        conv_chunk(smem, sbase, 0, 2, Nt + 0 * 4096, tid);
        conv_chunk(smem, sbase, 1, 3, Nt + 1 * 4096, tid);

        __syncthreads();   // bar D: V visible (P already visible via bar C)

        // ---- O += P V (single x single, trans B) ----
#pragma unroll 1
        for (int kk = 0; kk < 8; kk++) {
            uint32_t a[2][4];
#pragma unroll
            for (int im = 0; im < 2; im++) {
                const uint32_t ao = swoff(wm * 32 + im * 16 + (lane & 15),
                                          kk * 16 + (lane >> 4) * 8);
                ldsm4(a[im], smem + OFF_P + ao);
            }
#pragma unroll
            for (int j2 = 0; j2 < 2; j2++) {
                const uint32_t bo =
                    swoff(kk * 16 + (lane & 7) + ((lane >> 3) & 1) * 8,
                          wn * 32 + j2 * 16 + (lane >> 4) * 8);
                uint32_t bb[4];
                ldsm4t(bb, smem + OFF_KV + bo);
#pragma unroll
                for (int im = 0; im < 2; im++) {
                    mma16816(oacc[im][2 * j2 + 0], a[im], bb[0], bb[1]);
                    mma16816(oacc[im][2 * j2 + 1], a[im], bb[2], bb[3]);
                }
            }
        }
    }

    asm volatile("cp.async.wait_group 0;" ::: "memory");

    // ---- fold register rowsum partials into smem (once) ----
#pragma unroll
    for (int im = 0; im < 2; im++)
#pragma unroll
        for (int half = 0; half < 2; half++) {
            float r = rsacc[im][half];
            r += __shfl_xor_sync(0xffffffff, r, 1);
            r += __shfl_xor_sync(0xffffffff, r, 2);
            if ((lane & 3) == 0)
                atomicAdd(&rowsum[wm * 32 + im * 16 + (lane >> 2) + half * 8], r);
        }
    __syncthreads();
    if (tid < 128) rowsum[tid] = 1.f / rowsum[tid];
    __syncthreads();

    // ---- write context = O * rnorm ----
#pragma unroll
    for (int im = 0; im < 2; im++)
#pragma unroll
        for (int half = 0; half < 2; half++) {
            const int ql = wm * 32 + im * 16 + (lane >> 2) + half * 8;
            const float rn = rowsum[ql];
            float* crow = ctx + (size_t)ql * DD;
#pragma unroll
            for (int jn = 0; jn < 4; jn++) {
                const int d0 = wn * 32 + jn * 8 + (lane & 3) * 2;
                *reinterpret_cast<float2*>(crow + d0) =
                    make_float2(oacc[im][jn][half * 2 + 0] * rn,
                                oacc[im][jn][half * 2 + 1] * rn);
            }
        }

    // ---- normalize this CTA's attention slice in place (float4) ----
    float4* ap = reinterpret_cast<float4*>(att);
#pragma unroll 4
    for (int i = tid; i < 128 * SS / 4; i += NTH) {
        float rn = rowsum[i >> 9];   // 512 float4 per row
        float4 v = ap[i];
        v.x *= rn;
        v.y *= rn;
        v.z *= rn;
        v.w *= rn;
        ap[i] = v;
    }
}

// ---------------- launch ----------------
extern "C" void kernel_launch(void* const* d_in, const int* in_sizes, int n_in,
                              void* d_out, int out_size) {
    const float* Q = (const float*)d_in[0];
    const float* K = (const float*)d_in[1];
    const float* V = (const float*)d_in[2];
    const int*   M = (const int*)d_in[3];
    const float* scale = (const float*)d_in[4];
    float* out = (float*)d_out;

    cudaFuncSetAttribute(sdpa_kernel, cudaFuncAttributeMaxDynamicSharedMemorySize,
                         SMEM_SZ);
    sdpa_kernel<<<512, NTH, SMEM_SZ>>>(Q, K, V, M, scale, out);
}

// round 16
// speedup vs baseline: 3.2868x; 1.0442x over previous
#include <cuda_runtime.h>
#include <cuda_fp16.h>
#include <cstdint>

// Problem constants
#define SS 2048
#define DD 128
#define NTH 512
#define CTX_ELEMS ((size_t)2 * 16 * 2048 * 128)   // 8388608

// ---- dynamic smem byte offsets (swizzled buffers, 256 B row pitch) ----
#define OFF_Q   0                  // 128x128 fp16 single
#define OFF_KV  32768              // 128x128 fp16 (K then V), single
#define OFF_P   65536              // 128x128 fp16 single (masked)
#define OFF_STG 98304              // 4 slots x 16384 raw fp32 chunks
#define OFF_RS  163840             // float[128]
#define SMEM_SZ 164352

// ---------------- PTX helpers ----------------
__device__ __forceinline__ uint32_t smem_u32(const void* p) {
    return (uint32_t)__cvta_generic_to_shared(p);
}

// byte offset of fp16 element (r, c) in swizzled 128x128 tile (row = 256 B)
__device__ __forceinline__ uint32_t swoff(int r, int c) {
    return (uint32_t)(r * 256 + ((((c >> 3) ^ (r & 7)) << 4) | ((c & 7) << 1)));
}

__device__ __forceinline__ void ldsm4(uint32_t (&r)[4], const void* p) {
    uint32_t a = smem_u32(p);
    asm volatile("ldmatrix.sync.aligned.m8n8.x4.shared.b16 {%0,%1,%2,%3}, [%4];"
                 : "=r"(r[0]), "=r"(r[1]), "=r"(r[2]), "=r"(r[3]) : "r"(a));
}
__device__ __forceinline__ void ldsm4t(uint32_t (&r)[4], const void* p) {
    uint32_t a = smem_u32(p);
    asm volatile("ldmatrix.sync.aligned.m8n8.x4.trans.shared.b16 {%0,%1,%2,%3}, [%4];"
                 : "=r"(r[0]), "=r"(r[1]), "=r"(r[2]), "=r"(r[3]) : "r"(a));
}
__device__ __forceinline__ void mma16816(float (&c)[4], const uint32_t (&a)[4],
                                         uint32_t b0, uint32_t b1) {
    asm volatile(
        "mma.sync.aligned.m16n8k16.row.col.f32.f16.f16.f32 "
        "{%0,%1,%2,%3},{%4,%5,%6,%7},{%8,%9},{%0,%1,%2,%3};"
        : "+f"(c[0]), "+f"(c[1]), "+f"(c[2]), "+f"(c[3])
        : "r"(a[0]), "r"(a[1]), "r"(a[2]), "r"(a[3]), "r"(b0), "r"(b1));
}
__device__ __forceinline__ uint32_t pack2h(__half a, __half b) {
    __half2 t = __halves2half2(a, b);
    return *reinterpret_cast<uint32_t*>(&t);
}
__device__ __forceinline__ void cpasync16(uint32_t saddr, const void* g) {
    asm volatile("cp.async.cg.shared.global [%0], [%1], 16;"
                 :: "r"(saddr), "l"(g) : "memory");
}

// convert 8 fp32 -> single fp16
__device__ __forceinline__ void cvt8h(float4 v0, float4 v1, uint4& hi) {
    hi = make_uint4(
        pack2h(__float2half_rn(v0.x), __float2half_rn(v0.y)),
        pack2h(__float2half_rn(v0.z), __float2half_rn(v0.w)),
        pack2h(__float2half_rn(v1.x), __float2half_rn(v1.y)),
        pack2h(__float2half_rn(v1.z), __float2half_rn(v1.w)));
}

// stage one 16 KB chunk (32 rows x 128 fp32); thread stages its own 32 B
__device__ __forceinline__ void stage_chunk(uint32_t sbase, int slot,
                                            const float* gsrc, int tid) {
    uint32_t sa = sbase + OFF_STG + slot * 16384 + tid * 32;
    const char* g = reinterpret_cast<const char*>(gsrc) + tid * 32;
    cpasync16(sa, g);
    cpasync16(sa + 16, g + 16);
    asm volatile("cp.async.commit_group;" ::: "memory");
}

// barrier-free: wait own staged chunk (4-deep ring -> wait_group 3, fully
// prefetched one gemm-phase ahead), convert rows [ch*32,+32) into KV, then
// restage the freed slot with next_gsrc (prefetch distance 4 chunks).
__device__ __forceinline__ void conv_chunk(unsigned char* smem, uint32_t sbase,
                                           int slot, int ch,
                                           const float* next_gsrc, int tid) {
    asm volatile("cp.async.wait_group 3;" ::: "memory");
    const float* stg = reinterpret_cast<const float*>(smem + OFF_STG + slot * 16384);
    const int rl = tid >> 4;
    const int c  = (tid & 15) * 8;
    const int r  = ch * 32 + rl;
    float4 v0 = *reinterpret_cast<const float4*>(stg + rl * 128 + c);
    float4 v1 = *reinterpret_cast<const float4*>(stg + rl * 128 + c + 4);
    uint4 hi;
    cvt8h(v0, v1, hi);
    const uint32_t off = (uint32_t)(r * 256 + ((((c >> 3) ^ (r & 7))) << 4));
    *reinterpret_cast<uint4*>(smem + OFF_KV + off) = hi;
    stage_chunk(sbase, slot, next_gsrc, tid);
}

// ---------------- main kernel ----------------
__global__ void __launch_bounds__(NTH, 1)
sdpa_kernel(const float* __restrict__ Q, const float* __restrict__ K,
            const float* __restrict__ V, const int* __restrict__ mask,
            const float* __restrict__ scalep, float* __restrict__ out) {
    extern __shared__ unsigned char smem[];
    const uint32_t sbase = smem_u32(smem);
    float* rowsum = reinterpret_cast<float*>(smem + OFF_RS);

    const int tid  = threadIdx.x;
    const int lane = tid & 31;
    const int warp = tid >> 5;
    const int wm = warp >> 2;   // 0..3
    const int wn = warp & 3;    // 0..3

    const int bh = blockIdx.x >> 4;       // 0..31
    const int qt = blockIdx.x & 15;
    const int b  = bh >> 4;               // H = 16
    const int qbase = qt * 128;

    const float kscale = (*scalep) * 1.44269504088896340736f;  // scale*log2(e)
    const float* Qg = Q + ((size_t)bh * SS + qbase) * DD;
    const float* Kg = K + (size_t)bh * SS * DD;
    const float* Vg = V + (size_t)bh * SS * DD;
    const int*   mb = mask + (size_t)b * SS * SS;
    float* ctx = out + ((size_t)bh * SS + qbase) * DD;
    float* att = out + CTX_ELEMS + ((size_t)bh * SS + qbase) * SS;

    // prologue: stage ALL 4 K(0) chunks; Q -> single fp16
    stage_chunk(sbase, 0, Kg + 0 * 4096, tid);
    stage_chunk(sbase, 1, Kg + 1 * 4096, tid);
    stage_chunk(sbase, 2, Kg + 2 * 4096, tid);
    stage_chunk(sbase, 3, Kg + 3 * 4096, tid);
    if (tid < 128) rowsum[tid] = 0.f;
#pragma unroll 1
    for (int pass = 0; pass < 4; pass++) {
        const int r = pass * 32 + (tid >> 4);
        const int c = (tid & 15) * 8;
        float4 v0 = *reinterpret_cast<const float4*>(Qg + (size_t)r * DD + c);
        float4 v1 = *reinterpret_cast<const float4*>(Qg + (size_t)r * DD + c + 4);
        uint4 hi;
        cvt8h(v0, v1, hi);
        const uint32_t off = (uint32_t)(r * 256 + ((((c >> 3) ^ (r & 7))) << 4));
        *reinterpret_cast<uint4*>(smem + OFF_Q + off) = hi;
    }

    float oacc[2][4][4];
#pragma unroll
    for (int im = 0; im < 2; im++)
#pragma unroll
        for (int j = 0; j < 4; j++)
#pragma unroll
            for (int c = 0; c < 4; c++) oacc[im][j][c] = 0.f;

    // per-thread rowsum partials, accumulated across all k-tiles
    float rsacc[2][2] = {{0.f, 0.f}, {0.f, 0.f}};

#pragma unroll 1
    for (int kt = 0; kt < SS / 128; kt++) {
        const float* Vt = Vg + (size_t)kt * 128 * DD;
        const float* Nt = (kt + 1 < SS / 128) ? Kg + (size_t)(kt + 1) * 128 * DD : Kg;

        __syncthreads();   // bar A: prev PV done reading KV(V)

        // convert K chunks (staged a full phase ago); restage V chunks
        conv_chunk(smem, sbase, 0, 0, Vt + 0 * 4096, tid);
        conv_chunk(smem, sbase, 1, 1, Vt + 1 * 4096, tid);
        conv_chunk(smem, sbase, 2, 2, Vt + 2 * 4096, tid);
        conv_chunk(smem, sbase, 3, 3, Vt + 3 * 4096, tid);

        __syncthreads();   // bar B: K tile visible

        // ---- S = Q K^T (single fp16 x single fp16) ----
        float sacc[2][4][4];
#pragma unroll
        for (int im = 0; im < 2; im++)
#pragma unroll
            for (int j = 0; j < 4; j++)
#pragma unroll
                for (int c = 0; c < 4; c++) sacc[im][j][c] = 0.f;

#pragma unroll 1
        for (int kk = 0; kk < 8; kk++) {
            uint32_t a[2][4];
#pragma unroll
            for (int im = 0; im < 2; im++) {
                const uint32_t ao = swoff(wm * 32 + im * 16 + (lane & 15),
                                          kk * 16 + (lane >> 4) * 8);
                ldsm4(a[im], smem + OFF_Q + ao);
            }
#pragma unroll
            for (int j2 = 0; j2 < 2; j2++) {
                const uint32_t bo =
                    swoff(wn * 32 + j2 * 16 + (lane >> 4) * 8 + (lane & 7),
                          kk * 16 + ((lane >> 3) & 1) * 8);
                uint32_t bb[4];
                ldsm4(bb, smem + OFF_KV + bo);
#pragma unroll
                for (int im = 0; im < 2; im++) {
                    mma16816(sacc[im][2 * j2 + 0], a[im], bb[0], bb[1]);
                    mma16816(sacc[im][2 * j2 + 1], a[im], bb[2], bb[3]);
                }
            }
        }

        // ---- fused epilogue: mask + exp2 + att write + masked P store ----
#pragma unroll
        for (int im = 0; im < 2; im++) {
#pragma unroll
            for (int half = 0; half < 2; half++) {
                const int ql = wm * 32 + im * 16 + (lane >> 2) + half * 8;
                const int* mrow = mb + (size_t)(qbase + ql) * SS + kt * 128;
                float* arow = att + (size_t)ql * SS + kt * 128;
                int2 mv[4];
#pragma unroll
                for (int jn = 0; jn < 4; jn++)
                    mv[jn] = *reinterpret_cast<const int2*>(
                        mrow + wn * 32 + jn * 8 + (lane & 3) * 2);
                float rs = 0.f;
#pragma unroll
                for (int jn = 0; jn < 4; jn++) {
                    const int nc = wn * 32 + jn * 8 + (lane & 3) * 2;
                    float e0 = mv[jn].x ? exp2f(sacc[im][jn][half * 2 + 0] * kscale) : 0.f;
                    float e1 = mv[jn].y ? exp2f(sacc[im][jn][half * 2 + 1] * kscale) : 0.f;
                    *reinterpret_cast<float2*>(arow + nc) = make_float2(e0, e1);
                    rs += e0 + e1;
                    const uint32_t po = swoff(ql, nc);
                    *reinterpret_cast<uint32_t*>(smem + OFF_P + po) =
                        pack2h(__float2half_rn(e0), __float2half_rn(e1));
                }
                rsacc[im][half] += rs;
            }
        }

        __syncthreads();   // bar C: P visible; S-gemm KV reads done

        // convert V chunks; restage next-K chunks
        conv_chunk(smem, sbase, 0, 0, Nt + 0 * 4096, tid);
        conv_chunk(smem, sbase, 1, 1, Nt + 1 * 4096, tid);
        conv_chunk(smem, sbase, 2, 2, Nt + 2 * 4096, tid);
        conv_chunk(smem, sbase, 3, 3, Nt + 3 * 4096, tid);

        __syncthreads();   // bar D: V visible

        // ---- O += P V (single x single, trans B) ----
#pragma unroll 1
        for (int kk = 0; kk < 8; kk++) {
            uint32_t a[2][4];
#pragma unroll
            for (int im = 0; im < 2; im++) {
                const uint32_t ao = swoff(wm * 32 + im * 16 + (lane & 15),
                                          kk * 16 + (lane >> 4) * 8);
                ldsm4(a[im], smem + OFF_P + ao);
            }
#pragma unroll
            for (int j2 = 0; j2 < 2; j2++) {
                const uint32_t bo =
                    swoff(kk * 16 + (lane & 7) + ((lane >> 3) & 1) * 8,
                          wn * 32 + j2 * 16 + (lane >> 4) * 8);
                uint32_t bb[4];
                ldsm4t(bb, smem + OFF_KV + bo);
#pragma unroll
                for (int im = 0; im < 2; im++) {
                    mma16816(oacc[im][2 * j2 + 0], a[im], bb[0], bb[1]);
                    mma16816(oacc[im][2 * j2 + 1], a[im], bb[2], bb[3]);
                }
            }
        }
    }

    asm volatile("cp.async.wait_group 0;" ::: "memory");

    // ---- fold register rowsum partials into smem (once) ----
#pragma unroll
    for (int im = 0; im < 2; im++)
#pragma unroll
        for (int half = 0; half < 2; half++) {
            float r = rsacc[im][half];
            r += __shfl_xor_sync(0xffffffff, r, 1);
            r += __shfl_xor_sync(0xffffffff, r, 2);
            if ((lane & 3) == 0)
                atomicAdd(&rowsum[wm * 32 + im * 16 + (lane >> 2) + half * 8], r);
        }
    __syncthreads();
    if (tid < 128) rowsum[tid] = 1.f / rowsum[tid];
    __syncthreads();

    // ---- write context = O * rnorm ----
#pragma unroll
    for (int im = 0; im < 2; im++)
#pragma unroll
        for (int half = 0; half < 2; half++) {
            const int ql = wm * 32 + im * 16 + (lane >> 2) + half * 8;
            const float rn = rowsum[ql];
            float* crow = ctx + (size_t)ql * DD;
#pragma unroll
            for (int jn = 0; jn < 4; jn++) {
                const int d0 = wn * 32 + jn * 8 + (lane & 3) * 2;
                *reinterpret_cast<float2*>(crow + d0) =
                    make_float2(oacc[im][jn][half * 2 + 0] * rn,
                                oacc[im][jn][half * 2 + 1] * rn);
            }
        }

    // ---- normalize this CTA's attention slice in place (float4) ----
    float4* ap = reinterpret_cast<float4*>(att);
#pragma unroll 4
    for (int i = tid; i < 128 * SS / 4; i += NTH) {
        float rn = rowsum[i >> 9];   // 512 float4 per row
        float4 v = ap[i];
        v.x *= rn;
        v.y *= rn;
        v.z *= rn;
        v.w *= rn;
        ap[i] = v;
    }
}

// ---------------- launch ----------------
extern "C" void kernel_launch(void* const* d_in, const int* in_sizes, int n_in,
                              void* d_out, int out_size) {
    const float* Q = (const float*)d_in[0];
    const float* K = (const float*)d_in[1];
    const float* V = (const float*)d_in[2];
    const int*   M = (const int*)d_in[3];
    const float* scale = (const float*)d_in[4];
    float* out = (float*)d_out;

    cudaFuncSetAttribute(sdpa_kernel, cudaFuncAttributeMaxDynamicSharedMemorySize,
                         SMEM_SZ);
    sdpa_kernel<<<512, NTH, SMEM_SZ>>>(Q, K, V, M, scale, out);
}

// round 17
// speedup vs baseline: 3.6008x; 1.0955x over previous
#include <cuda_runtime.h>
#include <cuda_fp16.h>
#include <cstdint>

// Problem constants
#define SS 2048
#define DD 128
#define NTH 512
#define CTX_ELEMS ((size_t)2 * 16 * 2048 * 128)   // 8388608
#define NWORDS (2 * 2048 * 64)                    // bitmask words (1 MB)

// ---- dynamic smem byte offsets (swizzled buffers, 256 B row pitch) ----
#define OFF_Q   0                  // 128x128 fp16 single
#define OFF_KV  32768              // 128x128 fp16 (K then V), single
#define OFF_P   65536              // 128x128 fp16 single (masked)
#define OFF_STG 98304              // 4 slots x 16384 raw fp32 chunks
#define OFF_RS  163840             // float[128]
#define SMEM_SZ 164352

// packed mask bits: word (b*2048 + row)*64 + wc covers cols wc*32..wc*32+31
__device__ uint32_t g_mbits[NWORDS];

// ---------------- PTX helpers ----------------
__device__ __forceinline__ uint32_t smem_u32(const void* p) {
    return (uint32_t)__cvta_generic_to_shared(p);
}

// byte offset of fp16 element (r, c) in swizzled 128x128 tile (row = 256 B)
__device__ __forceinline__ uint32_t swoff(int r, int c) {
    return (uint32_t)(r * 256 + ((((c >> 3) ^ (r & 7)) << 4) | ((c & 7) << 1)));
}

__device__ __forceinline__ void ldsm4(uint32_t (&r)[4], const void* p) {
    uint32_t a = smem_u32(p);
    asm volatile("ldmatrix.sync.aligned.m8n8.x4.shared.b16 {%0,%1,%2,%3}, [%4];"
                 : "=r"(r[0]), "=r"(r[1]), "=r"(r[2]), "=r"(r[3]) : "r"(a));
}
__device__ __forceinline__ void ldsm4t(uint32_t (&r)[4], const void* p) {
    uint32_t a = smem_u32(p);
    asm volatile("ldmatrix.sync.aligned.m8n8.x4.trans.shared.b16 {%0,%1,%2,%3}, [%4];"
                 : "=r"(r[0]), "=r"(r[1]), "=r"(r[2]), "=r"(r[3]) : "r"(a));
}
__device__ __forceinline__ void mma16816(float (&c)[4], const uint32_t (&a)[4],
                                         uint32_t b0, uint32_t b1) {
    asm volatile(
        "mma.sync.aligned.m16n8k16.row.col.f32.f16.f16.f32 "
        "{%0,%1,%2,%3},{%4,%5,%6,%7},{%8,%9},{%0,%1,%2,%3};"
        : "+f"(c[0]), "+f"(c[1]), "+f"(c[2]), "+f"(c[3])
        : "r"(a[0]), "r"(a[1]), "r"(a[2]), "r"(a[3]), "r"(b0), "r"(b1));
}
__device__ __forceinline__ uint32_t pack2h(__half a, __half b) {
    __half2 t = __halves2half2(a, b);
    return *reinterpret_cast<uint32_t*>(&t);
}
__device__ __forceinline__ void cpasync16(uint32_t saddr, const void* g) {
    asm volatile("cp.async.cg.shared.global [%0], [%1], 16;"
                 :: "r"(saddr), "l"(g) : "memory");
}

// convert 8 fp32 -> single fp16
__device__ __forceinline__ void cvt8h(float4 v0, float4 v1, uint4& hi) {
    hi = make_uint4(
        pack2h(__float2half_rn(v0.x), __float2half_rn(v0.y)),
        pack2h(__float2half_rn(v0.z), __float2half_rn(v0.w)),
        pack2h(__float2half_rn(v1.x), __float2half_rn(v1.y)),
        pack2h(__float2half_rn(v1.z), __float2half_rn(v1.w)));
}

// stage one 16 KB chunk (32 rows x 128 fp32); thread stages its own 32 B
__device__ __forceinline__ void stage_chunk(uint32_t sbase, int slot,
                                            const float* gsrc, int tid) {
    uint32_t sa = sbase + OFF_STG + slot * 16384 + tid * 32;
    const char* g = reinterpret_cast<const char*>(gsrc) + tid * 32;
    cpasync16(sa, g);
    cpasync16(sa + 16, g + 16);
    asm volatile("cp.async.commit_group;" ::: "memory");
}

// barrier-free: wait own staged chunk (4-deep ring, prefetched a full
// gemm-phase ahead), convert rows [ch*32,+32) into KV, restage with next.
__device__ __forceinline__ void conv_chunk(unsigned char* smem, uint32_t sbase,
                                           int slot, int ch,
                                           const float* next_gsrc, int tid) {
    asm volatile("cp.async.wait_group 3;" ::: "memory");
    const float* stg = reinterpret_cast<const float*>(smem + OFF_STG + slot * 16384);
    const int rl = tid >> 4;
    const int c  = (tid & 15) * 8;
    const int r  = ch * 32 + rl;
    float4 v0 = *reinterpret_cast<const float4*>(stg + rl * 128 + c);
    float4 v1 = *reinterpret_cast<const float4*>(stg + rl * 128 + c + 4);
    uint4 hi;
    cvt8h(v0, v1, hi);
    const uint32_t off = (uint32_t)(r * 256 + ((((c >> 3) ^ (r & 7))) << 4));
    *reinterpret_cast<uint4*>(smem + OFF_KV + off) = hi;
    stage_chunk(sbase, slot, next_gsrc, tid);
}

// ---------------- mask pack kernel (1 bit per mask int) ----------------
__global__ void mask_pack_kernel(const int* __restrict__ mask) {
    const int w = blockIdx.x * blockDim.x + threadIdx.x;
    if (w >= NWORDS) return;
    const int4* src = reinterpret_cast<const int4*>(mask + (size_t)w * 32);
    uint32_t bits = 0;
#pragma unroll
    for (int j = 0; j < 8; j++) {
        int4 v = src[j];
        bits |= (uint32_t)(v.x != 0) << (j * 4 + 0);
        bits |= (uint32_t)(v.y != 0) << (j * 4 + 1);
        bits |= (uint32_t)(v.z != 0) << (j * 4 + 2);
        bits |= (uint32_t)(v.w != 0) << (j * 4 + 3);
    }
    g_mbits[w] = bits;
}

// ---------------- main kernel ----------------
__global__ void __launch_bounds__(NTH, 1)
sdpa_kernel(const float* __restrict__ Q, const float* __restrict__ K,
            const float* __restrict__ V,
            const float* __restrict__ scalep, float* __restrict__ out) {
    extern __shared__ unsigned char smem[];
    const uint32_t sbase = smem_u32(smem);
    float* rowsum = reinterpret_cast<float*>(smem + OFF_RS);

    const int tid  = threadIdx.x;
    const int lane = tid & 31;
    const int warp = tid >> 5;
    const int wm = warp >> 2;   // 0..3
    const int wn = warp & 3;    // 0..3

    const int bh = blockIdx.x >> 4;       // 0..31
    const int qt = blockIdx.x & 15;
    const int b  = bh >> 4;               // H = 16
    const int qbase = qt * 128;

    const float kscale = (*scalep) * 1.44269504088896340736f;  // scale*log2(e)
    const float* Qg = Q + ((size_t)bh * SS + qbase) * DD;
    const float* Kg = K + (size_t)bh * SS * DD;
    const float* Vg = V + (size_t)bh * SS * DD;
    const uint32_t* mbits = g_mbits + ((size_t)b * SS + qbase) * 64;
    float* ctx = out + ((size_t)bh * SS + qbase) * DD;
    float* att = out + CTX_ELEMS + ((size_t)bh * SS + qbase) * SS;

    // prologue: stage ALL 4 K(0) chunks; Q -> single fp16
    stage_chunk(sbase, 0, Kg + 0 * 4096, tid);
    stage_chunk(sbase, 1, Kg + 1 * 4096, tid);
    stage_chunk(sbase, 2, Kg + 2 * 4096, tid);
    stage_chunk(sbase, 3, Kg + 3 * 4096, tid);
    if (tid < 128) rowsum[tid] = 0.f;
#pragma unroll 1
    for (int pass = 0; pass < 4; pass++) {
        const int r = pass * 32 + (tid >> 4);
        const int c = (tid & 15) * 8;
        float4 v0 = *reinterpret_cast<const float4*>(Qg + (size_t)r * DD + c);
        float4 v1 = *reinterpret_cast<const float4*>(Qg + (size_t)r * DD + c + 4);
        uint4 hi;
        cvt8h(v0, v1, hi);
        const uint32_t off = (uint32_t)(r * 256 + ((((c >> 3) ^ (r & 7))) << 4));
        *reinterpret_cast<uint4*>(smem + OFF_Q + off) = hi;
    }

    float oacc[2][4][4];
#pragma unroll
    for (int im = 0; im < 2; im++)
#pragma unroll
        for (int j = 0; j < 4; j++)
#pragma unroll
            for (int c = 0; c < 4; c++) oacc[im][j][c] = 0.f;

    // per-thread rowsum partials, accumulated across all k-tiles
    float rsacc[2][2] = {{0.f, 0.f}, {0.f, 0.f}};

#pragma unroll 1
    for (int kt = 0; kt < SS / 128; kt++) {
        const float* Vt = Vg + (size_t)kt * 128 * DD;
        const float* Nt = (kt + 1 < SS / 128) ? Kg + (size_t)(kt + 1) * 128 * DD : Kg;

        __syncthreads();   // bar A: prev PV done reading KV(V)

        // convert K chunks (staged a full phase ago); restage V chunks
        conv_chunk(smem, sbase, 0, 0, Vt + 0 * 4096, tid);
        conv_chunk(smem, sbase, 1, 1, Vt + 1 * 4096, tid);
        conv_chunk(smem, sbase, 2, 2, Vt + 2 * 4096, tid);
        conv_chunk(smem, sbase, 3, 3, Vt + 3 * 4096, tid);

        __syncthreads();   // bar B: K tile visible

        // ---- S = Q K^T (single fp16 x single fp16) ----
        float sacc[2][4][4];
#pragma unroll
        for (int im = 0; im < 2; im++)
#pragma unroll
            for (int j = 0; j < 4; j++)
#pragma unroll
                for (int c = 0; c < 4; c++) sacc[im][j][c] = 0.f;

#pragma unroll 1
        for (int kk = 0; kk < 8; kk++) {
            uint32_t a[2][4];
#pragma unroll
            for (int im = 0; im < 2; im++) {
                const uint32_t ao = swoff(wm * 32 + im * 16 + (lane & 15),
                                          kk * 16 + (lane >> 4) * 8);
                ldsm4(a[im], smem + OFF_Q + ao);
            }
#pragma unroll
            for (int j2 = 0; j2 < 2; j2++) {
                const uint32_t bo =
                    swoff(wn * 32 + j2 * 16 + (lane >> 4) * 8 + (lane & 7),
                          kk * 16 + ((lane >> 3) & 1) * 8);
                uint32_t bb[4];
                ldsm4(bb, smem + OFF_KV + bo);
#pragma unroll
                for (int im = 0; im < 2; im++) {
                    mma16816(sacc[im][2 * j2 + 0], a[im], bb[0], bb[1]);
                    mma16816(sacc[im][2 * j2 + 1], a[im], bb[2], bb[3]);
                }
            }
        }

        // ---- fused epilogue: bitmask + exp2 + att write + masked P store ----
#pragma unroll
        for (int im = 0; im < 2; im++) {
#pragma unroll
            for (int half = 0; half < 2; half++) {
                const int ql = wm * 32 + im * 16 + (lane >> 2) + half * 8;
                float* arow = att + (size_t)ql * SS + kt * 128;
                // one bitmask word covers this thread's 32 cols (wn*32..+31)
                const uint32_t w = mbits[(size_t)ql * 64 + kt * 4 + wn];
                float rs = 0.f;
#pragma unroll
                for (int jn = 0; jn < 4; jn++) {
                    const int nc = wn * 32 + jn * 8 + (lane & 3) * 2;
                    const int p = jn * 8 + (lane & 3) * 2;
                    float e0 = (w >> p) & 1 ?
                        exp2f(sacc[im][jn][half * 2 + 0] * kscale) : 0.f;
                    float e1 = (w >> (p + 1)) & 1 ?
                        exp2f(sacc[im][jn][half * 2 + 1] * kscale) : 0.f;
                    *reinterpret_cast<float2*>(arow + nc) = make_float2(e0, e1);
                    rs += e0 + e1;
                    const uint32_t po = swoff(ql, nc);
                    *reinterpret_cast<uint32_t*>(smem + OFF_P + po) =
                        pack2h(__float2half_rn(e0), __float2half_rn(e1));
                }
                rsacc[im][half] += rs;
            }
        }

        __syncthreads();   // bar C: P visible; S-gemm KV reads done

        // convert V chunks; restage next-K chunks
        conv_chunk(smem, sbase, 0, 0, Nt + 0 * 4096, tid);
        conv_chunk(smem, sbase, 1, 1, Nt + 1 * 4096, tid);
        conv_chunk(smem, sbase, 2, 2, Nt + 2 * 4096, tid);
        conv_chunk(smem, sbase, 3, 3, Nt + 3 * 4096, tid);

        __syncthreads();   // bar D: V visible

        // ---- O += P V (single x single, trans B) ----
#pragma unroll 1
        for (int kk = 0; kk < 8; kk++) {
            uint32_t a[2][4];
#pragma unroll
            for (int im = 0; im < 2; im++) {
                const uint32_t ao = swoff(wm * 32 + im * 16 + (lane & 15),
                                          kk * 16 + (lane >> 4) * 8);
                ldsm4(a[im], smem + OFF_P + ao);
            }
#pragma unroll
            for (int j2 = 0; j2 < 2; j2++) {
                const uint32_t bo =
                    swoff(kk * 16 + (lane & 7) + ((lane >> 3) & 1) * 8,
                          wn * 32 + j2 * 16 + (lane >> 4) * 8);
                uint32_t bb[4];
                ldsm4t(bb, smem + OFF_KV + bo);
#pragma unroll
                for (int im = 0; im < 2; im++) {
                    mma16816(oacc[im][2 * j2 + 0], a[im], bb[0], bb[1]);
                    mma16816(oacc[im][2 * j2 + 1], a[im], bb[2], bb[3]);
                }
            }
        }
    }

    asm volatile("cp.async.wait_group 0;" ::: "memory");

    // ---- fold register rowsum partials into smem (once) ----
#pragma unroll
    for (int im = 0; im < 2; im++)
#pragma unroll
        for (int half = 0; half < 2; half++) {
            float r = rsacc[im][half];
            r += __shfl_xor_sync(0xffffffff, r, 1);
            r += __shfl_xor_sync(0xffffffff, r, 2);
            if ((lane & 3) == 0)
                atomicAdd(&rowsum[wm * 32 + im * 16 + (lane >> 2) + half * 8], r);
        }
    __syncthreads();
    if (tid < 128) rowsum[tid] = 1.f / rowsum[tid];
    __syncthreads();

    // ---- write context = O * rnorm ----
#pragma unroll
    for (int im = 0; im < 2; im++)
#pragma unroll
        for (int half = 0; half < 2; half++) {
            const int ql = wm * 32 + im * 16 + (lane >> 2) + half * 8;
            const float rn = rowsum[ql];
            float* crow = ctx + (size_t)ql * DD;
#pragma unroll
            for (int jn = 0; jn < 4; jn++) {
                const int d0 = wn * 32 + jn * 8 + (lane & 3) * 2;
                *reinterpret_cast<float2*>(crow + d0) =
                    make_float2(oacc[im][jn][half * 2 + 0] * rn,
                                oacc[im][jn][half * 2 + 1] * rn);
            }
        }

    // ---- normalize this CTA's attention slice in place (float4) ----
    float4* ap = reinterpret_cast<float4*>(att);
#pragma unroll 4
    for (int i = tid; i < 128 * SS / 4; i += NTH) {
        float rn = rowsum[i >> 9];   // 512 float4 per row
        float4 v = ap[i];
        v.x *= rn;
        v.y *= rn;
        v.z *= rn;
        v.w *= rn;
        ap[i] = v;
    }
}

// ---------------- launch ----------------
extern "C" void kernel_launch(void* const* d_in, const int* in_sizes, int n_in,
                              void* d_out, int out_size) {
    const float* Q = (const float*)d_in[0];
    const float* K = (const float*)d_in[1];
    const float* V = (const float*)d_in[2];
    const int*   M = (const int*)d_in[3];
    const float* scale = (const float*)d_in[4];
    float* out = (float*)d_out;

    mask_pack_kernel<<<NWORDS / 256, 256>>>(M);

    cudaFuncSetAttribute(sdpa_kernel, cudaFuncAttributeMaxDynamicSharedMemorySize,
                         SMEM_SZ);
    sdpa_kernel<<<512, NTH, SMEM_SZ>>>(Q, K, V, scale, out);
}